// round 7
// baseline (speedup 1.0000x reference)
#include <cuda_runtime.h>
#include <cuda_bf16.h>
#include <math.h>
#include <stdint.h>

// Problem dims
#define BB 16
#define TT 512
#define CC 2048
#define HH 16
#define HD 128
#define ROPE_D 16
#define M1 (BB*TT)        // 8192
#define N1 (3*CC)         // 6144
#define K1 CC             // 2048

// ---------------- scratch (device globals; no allocation allowed) ----------
__device__ float g_qkv[(size_t)M1 * N1];                 // [8192,6144]

// bf16 hi/lo scratch
__device__ __nv_bfloat16 g_xh[(size_t)M1 * K1];
__device__ __nv_bfloat16 g_xl[(size_t)M1 * K1];
__device__ __nv_bfloat16 g_wqh[(size_t)N1 * K1];         // Wqkv^T [6144,2048]
__device__ __nv_bfloat16 g_wql[(size_t)N1 * K1];
__device__ __nv_bfloat16 g_woh[(size_t)CC * CC];         // Wout^T [2048,2048]
__device__ __nv_bfloat16 g_wol[(size_t)CC * CC];
__device__ __nv_bfloat16 g_yh[(size_t)M1 * CC];
__device__ __nv_bfloat16 g_yl[(size_t)M1 * CC];
// q/k/v hi/lo, [B*H, T, 128]
__device__ __nv_bfloat16 g_q_h[(size_t)BB*HH*TT*HD];
__device__ __nv_bfloat16 g_q_l[(size_t)BB*HH*TT*HD];
__device__ __nv_bfloat16 g_k_h[(size_t)BB*HH*TT*HD];
__device__ __nv_bfloat16 g_k_l[(size_t)BB*HH*TT*HD];
__device__ __nv_bfloat16 g_v_h[(size_t)BB*HH*TT*HD];
__device__ __nv_bfloat16 g_v_l[(size_t)BB*HH*TT*HD];

// ======================= PTX helpers (baseline ISA only) ===================
__device__ __forceinline__ uint32_t smem_u32(const void* p) {
    uint32_t a;
    asm("{ .reg .u64 t; cvta.to.shared.u64 t, %1; cvt.u32.u64 %0, t; }"
        : "=r"(a) : "l"(p));
    return a;
}
__device__ __forceinline__ void cpasync16(uint32_t dst, const void* src) {
    asm volatile("cp.async.cg.shared.global [%0], [%1], 16;"
                 :: "r"(dst), "l"(src) : "memory");
}
__device__ __forceinline__ void cpasync_commit() {
    asm volatile("cp.async.commit_group;" ::: "memory");
}
__device__ __forceinline__ void cpasync_wait1() {
    asm volatile("cp.async.wait_group 1;" ::: "memory");
}
__device__ __forceinline__ void ldsm_x4(uint32_t& r0, uint32_t& r1,
                                        uint32_t& r2, uint32_t& r3, uint32_t a) {
    asm volatile("ldmatrix.sync.aligned.m8n8.x4.shared.b16 {%0,%1,%2,%3}, [%4];"
                 : "=r"(r0), "=r"(r1), "=r"(r2), "=r"(r3) : "r"(a));
}
__device__ __forceinline__ void ldsm_x4_t(uint32_t& r0, uint32_t& r1,
                                          uint32_t& r2, uint32_t& r3, uint32_t a) {
    asm volatile("ldmatrix.sync.aligned.m8n8.x4.trans.shared.b16 {%0,%1,%2,%3}, [%4];"
                 : "=r"(r0), "=r"(r1), "=r"(r2), "=r"(r3) : "r"(a));
}
__device__ __forceinline__ void mma16816(float* d, const uint32_t* a,
                                         const uint32_t* b) {
    asm volatile(
        "mma.sync.aligned.m16n8k16.row.col.f32.bf16.bf16.f32 "
        "{%0,%1,%2,%3}, {%4,%5,%6,%7}, {%8,%9}, {%0,%1,%2,%3};"
        : "+f"(d[0]), "+f"(d[1]), "+f"(d[2]), "+f"(d[3])
        : "r"(a[0]), "r"(a[1]), "r"(a[2]), "r"(a[3]), "r"(b[0]), "r"(b[1]));
}
__device__ __forceinline__ uint32_t packbf(float a, float b) {
    __nv_bfloat162 t = __floats2bfloat162_rn(a, b);
    return *reinterpret_cast<uint32_t*>(&t);
}
// hi/lo split of two floats into packed bf16x2 words
__device__ __forceinline__ void split2(float a, float b, uint32_t& hi, uint32_t& lo) {
    float ah = __bfloat162float(__float2bfloat16(a));
    float bh = __bfloat162float(__float2bfloat16(b));
    hi = packbf(ah, bh);
    lo = packbf(a - ah, b - bh);
}

// ======================= mma.sync split-bf16 GEMM ==========================
#define GBM 128
#define GBN 128
#define GBK 32
#define TILE_B (128 * 64)            // 8192 B per tile
#define STG_B  (4 * TILE_B)          // Ah, Al, Bh, Bl = 32768
#define NSTAGE 3

// conflict-free smem offset: row stride 64B, chunk (16B) XOR'd with (row>>1)&3
__device__ __forceinline__ uint32_t swz(int row, int chunk) {
    return (uint32_t)((row << 6) + ((chunk ^ ((row >> 1) & 3)) << 4));
}

__device__ __forceinline__ void g2s_stage(
    uint32_t sbase,
    const __nv_bfloat16* __restrict__ Ah, const __nv_bfloat16* __restrict__ Al,
    const __nv_bfloat16* __restrict__ Bh, const __nv_bfloat16* __restrict__ Bl,
    int m0, int n0, int k0, int K, int tid)
{
#pragma unroll
    for (int i = 0; i < 2; i++) {
        int s = tid + i * 256;               // 0..511
        int r = s >> 2, c = s & 3;           // row 0..127, 16B chunk 0..3
        uint32_t so = swz(r, c);
        size_t ga = (size_t)(m0 + r) * K + k0 + c * 8;
        size_t gb = (size_t)(n0 + r) * K + k0 + c * 8;
        cpasync16(sbase + 0 * TILE_B + so, Ah + ga);
        cpasync16(sbase + 1 * TILE_B + so, Al + ga);
        cpasync16(sbase + 2 * TILE_B + so, Bh + gb);
        cpasync16(sbase + 3 * TILE_B + so, Bl + gb);
    }
}

__global__ __launch_bounds__(256, 2)
void gemm_mma_kernel(const __nv_bfloat16* __restrict__ Ah,
                     const __nv_bfloat16* __restrict__ Al,
                     const __nv_bfloat16* __restrict__ Bh,
                     const __nv_bfloat16* __restrict__ Bl,
                     float* __restrict__ C, int M, int N, int K)
{
    extern __shared__ char sm_raw[];
    const uint32_t smbase = smem_u32(sm_raw);
    const int tid = threadIdx.x, wid = tid >> 5, lane = tid & 31;
    const int wm = (wid >> 2) * 64;
    const int wn = (wid & 3) * 32;
    const int m0 = blockIdx.y * GBM;
    const int n0 = blockIdx.x * GBN;
    const int lrow = lane & 15;
    const int lch  = (lane >> 4) & 1;

    float acc[4][4][4];
#pragma unroll
    for (int a = 0; a < 4; a++)
#pragma unroll
        for (int b = 0; b < 4; b++)
#pragma unroll
            for (int c = 0; c < 4; c++) acc[a][b][c] = 0.0f;

    g2s_stage(smbase + 0 * STG_B, Ah, Al, Bh, Bl, m0, n0, 0, K, tid);
    cpasync_commit();
    g2s_stage(smbase + 1 * STG_B, Ah, Al, Bh, Bl, m0, n0, GBK, K, tid);
    cpasync_commit();

    const int niter = K / GBK;               // 64
    int stage = 0, nstage = 2;
    for (int it = 0; it < niter; ++it) {
        cpasync_wait1();
        __syncthreads();

        if (it + 2 < niter)
            g2s_stage(smbase + nstage * STG_B, Ah, Al, Bh, Bl,
                      m0, n0, (it + 2) * GBK, K, tid);
        cpasync_commit();
        if (++nstage == NSTAGE) nstage = 0;

        const uint32_t sb = smbase + stage * STG_B;
        if (++stage == NSTAGE) stage = 0;

#pragma unroll
        for (int kb = 0; kb < 2; ++kb) {
            const int chunk = kb * 2 + lch;
            uint32_t ah[4][4], al[4][4];
#pragma unroll
            for (int mf = 0; mf < 4; ++mf) {
                uint32_t off = swz(wm + mf * 16 + lrow, chunk);
                ldsm_x4(ah[mf][0], ah[mf][1], ah[mf][2], ah[mf][3],
                        sb + 0 * TILE_B + off);
                ldsm_x4(al[mf][0], al[mf][1], al[mf][2], al[mf][3],
                        sb + 1 * TILE_B + off);
            }
            uint32_t bh[4][2], bl[4][2];
#pragma unroll
            for (int np = 0; np < 2; ++np) {
                uint32_t off = swz(wn + np * 16 + lrow, chunk);
                uint32_t r0, r1, r2, r3;
                ldsm_x4(r0, r1, r2, r3, sb + 2 * TILE_B + off);
                bh[np*2][0] = r0; bh[np*2][1] = r2;
                bh[np*2+1][0] = r1; bh[np*2+1][1] = r3;
                ldsm_x4(r0, r1, r2, r3, sb + 3 * TILE_B + off);
                bl[np*2][0] = r0; bl[np*2][1] = r2;
                bl[np*2+1][0] = r1; bl[np*2+1][1] = r3;
            }
#pragma unroll
            for (int mf = 0; mf < 4; ++mf)
#pragma unroll
                for (int nf = 0; nf < 4; ++nf) {
                    mma16816(acc[mf][nf], ah[mf], bh[nf]);
                    mma16816(acc[mf][nf], ah[mf], bl[nf]);
                    mma16816(acc[mf][nf], al[mf], bh[nf]);
                }
        }
    }

    // epilogue
    const int l4 = lane >> 2, l2 = (lane & 3) * 2;
#pragma unroll
    for (int mf = 0; mf < 4; ++mf) {
        int r0 = m0 + wm + mf * 16 + l4;
#pragma unroll
        for (int nf = 0; nf < 4; ++nf) {
            int cx = n0 + wn + nf * 8 + l2;
            *(float2*)&C[(size_t)r0 * N + cx] =
                make_float2(acc[mf][nf][0], acc[mf][nf][1]);
            *(float2*)&C[(size_t)(r0 + 8) * N + cx] =
                make_float2(acc[mf][nf][2], acc[mf][nf][3]);
        }
    }
}

// ======================= conversion kernels ================================
__global__ __launch_bounds__(256)
void split_kernel(const float* __restrict__ in, __nv_bfloat16* __restrict__ hi,
                  __nv_bfloat16* __restrict__ lo, size_t n)
{
    size_t i = ((size_t)blockIdx.x * blockDim.x + threadIdx.x) * 4;
    if (i >= n) return;
    float4 x = *(const float4*)(in + i);
    __nv_bfloat16 h0 = __float2bfloat16(x.x), h1 = __float2bfloat16(x.y);
    __nv_bfloat16 h2 = __float2bfloat16(x.z), h3 = __float2bfloat16(x.w);
    __nv_bfloat162* hp = (__nv_bfloat162*)(hi + i);
    __nv_bfloat162* lp = (__nv_bfloat162*)(lo + i);
    hp[0] = __nv_bfloat162(h0, h1);
    hp[1] = __nv_bfloat162(h2, h3);
    lp[0] = __nv_bfloat162(__float2bfloat16(x.x - __bfloat162float(h0)),
                           __float2bfloat16(x.y - __bfloat162float(h1)));
    lp[1] = __nv_bfloat162(__float2bfloat16(x.z - __bfloat162float(h2)),
                           __float2bfloat16(x.w - __bfloat162float(h3)));
}

// W [K,N] f32 -> Th/Tl [N,K] bf16
__global__ __launch_bounds__(256)
void transpose_split_kernel(const float* __restrict__ W,
                            __nv_bfloat16* __restrict__ Th,
                            __nv_bfloat16* __restrict__ Tl, int K, int N)
{
    __shared__ float tile[32][33];
    int n0 = blockIdx.x * 32, k0 = blockIdx.y * 32;
    int tx = threadIdx.x, ty = threadIdx.y;   // 32 x 8
#pragma unroll
    for (int i = 0; i < 32; i += 8)
        tile[ty + i][tx] = W[(size_t)(k0 + ty + i) * N + n0 + tx];
    __syncthreads();
#pragma unroll
    for (int i = 0; i < 32; i += 8) {
        float x = tile[tx][ty + i];
        __nv_bfloat16 h = __float2bfloat16(x);
        size_t o = (size_t)(n0 + ty + i) * K + k0 + tx;
        Th[o] = h;
        Tl[o] = __float2bfloat16(x - __bfloat162float(h));
    }
}

// ---------------- RoPE + split to bf16 hi/lo -------------------------------
__global__ __launch_bounds__(256)
void rope_split_kernel(const float* __restrict__ qkv,
                       __nv_bfloat16* __restrict__ qh, __nv_bfloat16* __restrict__ ql,
                       __nv_bfloat16* __restrict__ kh, __nv_bfloat16* __restrict__ kl,
                       __nv_bfloat16* __restrict__ vh, __nv_bfloat16* __restrict__ vl)
{
    size_t idx = (size_t)blockIdx.x * blockDim.x + threadIdx.x;
    if (idx >= (size_t)BB * TT * CC) return;
    int d = idx & (HD - 1);
    int h = (idx >> 7) & (HH - 1);
    int t = (idx >> 11) & (TT - 1);
    int b = idx >> 20;

    size_t srow = (size_t)(b * TT + t) * N1;
    size_t base = srow + h * HD + d;

    float qv = qkv[base];
    float kv = qkv[base + CC];
    float vv = qkv[base + 2 * CC];

    if (d < ROPE_D) {
        int j = (d < 8) ? d : d - 8;
        float freq = (float)t * powf(10000.0f, -(float)j / 8.0f);
        float c, s;
        sincosf(freq, &s, &c);
        if (d < 8) {
            float qo = qkv[base + 8];
            float ko = qkv[base + CC + 8];
            qv = qv * c - qo * s;
            kv = kv * c - ko * s;
        } else {
            float qo = qkv[base - 8];
            float ko = qkv[base + CC - 8];
            qv = qv * c + qo * s;
            kv = kv * c + ko * s;
        }
    }
    qv *= 0.08838834764831845f;   // fold 1/sqrt(128) into Q

    size_t dst = (((size_t)(b * HH + h)) * TT + t) * HD + d;
    float qhi = __bfloat162float(__float2bfloat16(qv));
    qh[dst] = __float2bfloat16(qv);
    ql[dst] = __float2bfloat16(qv - qhi);
    float khi = __bfloat162float(__float2bfloat16(kv));
    kh[dst] = __float2bfloat16(kv);
    kl[dst] = __float2bfloat16(kv - khi);
    float vhi = __bfloat162float(__float2bfloat16(vv));
    vh[dst] = __float2bfloat16(vv);
    vl[dst] = __float2bfloat16(vv - vhi);
}

// ---------------- Flash attention (mma.sync bf16x3, causal) ----------------
// CTA: 128 q-rows (8 warps x 16), kv tile 64, double-buffered KV pipeline.
// Smem rows are 256B with XOR swizzle (chunk ^= row&7) -> conflict-free LDSM.
#define AQ2 128
#define AKV 64
#define Q_TILE_B  (128 * 256)          // 32768 per Q array (hi or lo)
#define KV_TILE_B (64 * 256)           // 16384 per KV array
#define KV_STG_B  (4 * KV_TILE_B)      // Kh,Kl,Vh,Vl = 65536
#define FLASH_SMEM (2 * Q_TILE_B + 2 * KV_STG_B)   // 196608

__device__ __forceinline__ uint32_t aswz(int row, int chunk) {
    return (uint32_t)((row << 8) + ((chunk ^ (row & 7)) << 4));
}

__device__ __forceinline__ void kv_stage_load(
    uint32_t skv,
    const __nv_bfloat16* __restrict__ Kh, const __nv_bfloat16* __restrict__ Kl,
    const __nv_bfloat16* __restrict__ Vh, const __nv_bfloat16* __restrict__ Vl,
    size_t kg, int tid)
{
#pragma unroll
    for (int i = 0; i < 4; i++) {
        int s = tid + i * 256;            // 0..1023
        int r = s >> 4, c = s & 15;       // 64 rows x 16 chunks
        uint32_t so = aswz(r, c);
        size_t go = kg + (size_t)r * HD + c * 8;
        cpasync16(skv + 0 * KV_TILE_B + so, Kh + go);
        cpasync16(skv + 1 * KV_TILE_B + so, Kl + go);
        cpasync16(skv + 2 * KV_TILE_B + so, Vh + go);
        cpasync16(skv + 3 * KV_TILE_B + so, Vl + go);
    }
}

__global__ __launch_bounds__(256)
void flash_mma_kernel(const __nv_bfloat16* __restrict__ Qh, const __nv_bfloat16* __restrict__ Ql,
                      const __nv_bfloat16* __restrict__ Kh, const __nv_bfloat16* __restrict__ Kl,
                      const __nv_bfloat16* __restrict__ Vh, const __nv_bfloat16* __restrict__ Vl,
                      __nv_bfloat16* __restrict__ Yh, __nv_bfloat16* __restrict__ Yl)
{
    extern __shared__ char smraw[];
    const uint32_t sbse = smem_u32(smraw);
    const uint32_t sQh = sbse, sQl = sbse + Q_TILE_B;
    const uint32_t sKV0 = sbse + 2 * Q_TILE_B;

    const int tid = threadIdx.x, lane = tid & 31, wid = tid >> 5;
    const int qt = blockIdx.x, bhid = blockIdx.y;
    const int bb = bhid >> 4, hh = bhid & 15;
    const int q0 = qt * AQ2;
    const int l4 = lane >> 2, l2 = lane & 3;
    const int lrow = lane & 15, lch = lane >> 4;
    const int wq = wid * 16;                 // warp q-row base: 0..112

    const int jtmax = 2 * qt + 1;            // kv tiles 0..jtmax

    // G0: Q tile + KV stage 0
    const size_t qg = ((size_t)bhid * TT + q0) * HD;
#pragma unroll
    for (int i = 0; i < 8; i++) {
        int s = tid + i * 256;            // 0..2047
        int r = s >> 4, c = s & 15;       // 128 rows x 16 chunks
        uint32_t so = aswz(r, c);
        size_t go = qg + (size_t)r * HD + c * 8;
        cpasync16(sQh + so, Qh + go);
        cpasync16(sQl + so, Ql + go);
    }
    const size_t kvbase = (size_t)bhid * TT * HD;
    kv_stage_load(sKV0, Kh, Kl, Vh, Vl, kvbase, tid);
    cpasync_commit();
    // G1: KV stage 1 (jtmax >= 1 always)
    kv_stage_load(sKV0 + KV_STG_B, Kh, Kl, Vh, Vl, kvbase + (size_t)AKV * HD, tid);
    cpasync_commit();

    float m0 = -1e30f, m1 = -1e30f, l0 = 0.0f, l1 = 0.0f;
    float oacc[16][4];
#pragma unroll
    for (int i = 0; i < 16; i++)
#pragma unroll
        for (int j = 0; j < 4; j++) oacc[i][j] = 0.0f;

    for (int jt = 0; jt <= jtmax; ++jt) {
        cpasync_wait1();                 // stage jt resident (one group pending)
        __syncthreads();

        const uint32_t skv = sKV0 + (jt & 1) * KV_STG_B;
        const uint32_t sk_h = skv, sk_l = skv + KV_TILE_B;
        const uint32_t sv_h = skv + 2 * KV_TILE_B, sv_l = skv + 3 * KV_TILE_B;

        // ---- S = Q K^T (pre-scaled Q; fp32 acc; bf16x3) ----
        float sacc[8][4];
#pragma unroll
        for (int i = 0; i < 8; i++)
#pragma unroll
            for (int j = 0; j < 4; j++) sacc[i][j] = 0.0f;

#pragma unroll
        for (int kb = 0; kb < 8; ++kb) {
            const int chunk = kb * 2 + lch;
            const uint32_t qa = aswz(wq + lrow, chunk);
            uint32_t ah[4], al[4];
            ldsm_x4(ah[0], ah[1], ah[2], ah[3], sQh + qa);
            ldsm_x4(al[0], al[1], al[2], al[3], sQl + qa);
#pragma unroll
            for (int np = 0; np < 4; ++np) {
                const uint32_t ka = aswz(np * 16 + lrow, chunk);
                uint32_t r0, r1, r2, r3;
                ldsm_x4(r0, r1, r2, r3, sk_h + ka);
                uint32_t b0[2] = {r0, r2}, b1[2] = {r1, r3};
                ldsm_x4(r0, r1, r2, r3, sk_l + ka);
                uint32_t c0[2] = {r0, r2}, c1[2] = {r1, r3};
                mma16816(sacc[np*2],   ah, b0);
                mma16816(sacc[np*2],   ah, c0);
                mma16816(sacc[np*2],   al, b0);
                mma16816(sacc[np*2+1], ah, b1);
                mma16816(sacc[np*2+1], ah, c1);
                mma16816(sacc[np*2+1], al, b1);
            }
        }

        // ---- causal mask (diagonal-region tiles) ----
        if (jt >= 2 * qt) {
            const int r0g = q0 + wq + l4, r1g = r0g + 8;
#pragma unroll
            for (int nf = 0; nf < 8; ++nf) {
                int c0 = jt * AKV + nf * 8 + 2 * l2;
                if (c0     > r0g) sacc[nf][0] = -1e30f;
                if (c0 + 1 > r0g) sacc[nf][1] = -1e30f;
                if (c0     > r1g) sacc[nf][2] = -1e30f;
                if (c0 + 1 > r1g) sacc[nf][3] = -1e30f;
            }
        }

        // ---- online softmax ----
        float rx0 = -1e30f, rx1 = -1e30f;
#pragma unroll
        for (int nf = 0; nf < 8; ++nf) {
            rx0 = fmaxf(rx0, fmaxf(sacc[nf][0], sacc[nf][1]));
            rx1 = fmaxf(rx1, fmaxf(sacc[nf][2], sacc[nf][3]));
        }
#pragma unroll
        for (int off = 2; off >= 1; off >>= 1) {
            rx0 = fmaxf(rx0, __shfl_xor_sync(0xffffffffu, rx0, off));
            rx1 = fmaxf(rx1, __shfl_xor_sync(0xffffffffu, rx1, off));
        }
        float nm0 = fmaxf(m0, rx0), nm1 = fmaxf(m1, rx1);
        float a0 = __expf(m0 - nm0), a1 = __expf(m1 - nm1);
        m0 = nm0; m1 = nm1;
        float s0 = 0.0f, s1 = 0.0f;
#pragma unroll
        for (int nf = 0; nf < 8; ++nf) {
            sacc[nf][0] = __expf(sacc[nf][0] - nm0); s0 += sacc[nf][0];
            sacc[nf][1] = __expf(sacc[nf][1] - nm0); s0 += sacc[nf][1];
            sacc[nf][2] = __expf(sacc[nf][2] - nm1); s1 += sacc[nf][2];
            sacc[nf][3] = __expf(sacc[nf][3] - nm1); s1 += sacc[nf][3];
        }
#pragma unroll
        for (int off = 2; off >= 1; off >>= 1) {
            s0 += __shfl_xor_sync(0xffffffffu, s0, off);
            s1 += __shfl_xor_sync(0xffffffffu, s1, off);
        }
        l0 = l0 * a0 + s0;
        l1 = l1 * a1 + s1;
#pragma unroll
        for (int nt = 0; nt < 16; ++nt) {
            oacc[nt][0] *= a0; oacc[nt][1] *= a0;
            oacc[nt][2] *= a1; oacc[nt][3] *= a1;
        }

        // ---- O += P V ----
#pragma unroll
        for (int kt = 0; kt < 4; ++kt) {
            uint32_t ph[4], pl[4];
            split2(sacc[2*kt][0],   sacc[2*kt][1],   ph[0], pl[0]);
            split2(sacc[2*kt][2],   sacc[2*kt][3],   ph[1], pl[1]);
            split2(sacc[2*kt+1][0], sacc[2*kt+1][1], ph[2], pl[2]);
            split2(sacc[2*kt+1][2], sacc[2*kt+1][3], ph[3], pl[3]);
#pragma unroll
            for (int nd = 0; nd < 8; ++nd) {
                const uint32_t va = aswz(kt * 16 + lrow, nd * 2 + lch);
                uint32_t h0, h1, h2, h3, x0, x1, x2, x3;
                ldsm_x4_t(h0, h1, h2, h3, sv_h + va);
                ldsm_x4_t(x0, x1, x2, x3, sv_l + va);
                uint32_t vb0[2] = {h0, h1}, vb1[2] = {h2, h3};
                uint32_t wb0[2] = {x0, x1}, wb1[2] = {x2, x3};
                mma16816(oacc[nd*2],   ph, vb0);
                mma16816(oacc[nd*2],   ph, wb0);
                mma16816(oacc[nd*2],   pl, vb0);
                mma16816(oacc[nd*2+1], ph, vb1);
                mma16816(oacc[nd*2+1], ph, wb1);
                mma16816(oacc[nd*2+1], pl, vb1);
            }
        }

        // refill the stage just consumed (stage jt&1) for tile jt+2
        __syncthreads();
        if (jt + 2 <= jtmax)
            kv_stage_load(sKV0 + (jt & 1) * KV_STG_B, Kh, Kl, Vh, Vl,
                          kvbase + (size_t)(jt + 2) * AKV * HD, tid);
        cpasync_commit();                // one group per iter (may be empty)
    }

    // ---- epilogue: normalize, hi/lo split, write Yh/Yl [B,T,C] ----
    const float il0 = 1.0f / l0, il1 = 1.0f / l1;
    const int r0g = q0 + wq + l4, r1g = r0g + 8;
#pragma unroll
    for (int nt = 0; nt < 16; ++nt) {
        int col = hh * HD + nt * 8 + 2 * l2;
        size_t o0 = ((size_t)bb * TT + r0g) * CC + col;
        size_t o1 = ((size_t)bb * TT + r1g) * CC + col;
        uint32_t h, l;
        split2(oacc[nt][0] * il0, oacc[nt][1] * il0, h, l);
        *reinterpret_cast<uint32_t*>(Yh + o0) = h;
        *reinterpret_cast<uint32_t*>(Yl + o0) = l;
        split2(oacc[nt][2] * il1, oacc[nt][3] * il1, h, l);
        *reinterpret_cast<uint32_t*>(Yh + o1) = h;
        *reinterpret_cast<uint32_t*>(Yl + o1) = l;
    }
}

// ---------------- launch ----------------------------------------------------
extern "C" void kernel_launch(void* const* d_in, const int* in_sizes, int n_in,
                              void* d_out, int out_size)
{
    const float* x    = (const float*)d_in[0];
    const float* Wqkv = (const float*)d_in[1];
    const float* Wout = (const float*)d_in[2];
    float* out = (float*)d_out;

    float* qkv;
    cudaGetSymbolAddress((void**)&qkv, g_qkv);
    __nv_bfloat16 *xh, *xl, *wqh, *wql, *woh, *wol, *yh, *yl;
    __nv_bfloat16 *qh, *ql, *kh, *kl, *vh, *vl;
    cudaGetSymbolAddress((void**)&xh,  g_xh);
    cudaGetSymbolAddress((void**)&xl,  g_xl);
    cudaGetSymbolAddress((void**)&wqh, g_wqh);
    cudaGetSymbolAddress((void**)&wql, g_wql);
    cudaGetSymbolAddress((void**)&woh, g_woh);
    cudaGetSymbolAddress((void**)&wol, g_wol);
    cudaGetSymbolAddress((void**)&yh,  g_yh);
    cudaGetSymbolAddress((void**)&yl,  g_yl);
    cudaGetSymbolAddress((void**)&qh,  g_q_h);
    cudaGetSymbolAddress((void**)&ql,  g_q_l);
    cudaGetSymbolAddress((void**)&kh,  g_k_h);
    cudaGetSymbolAddress((void**)&kl,  g_k_l);
    cudaGetSymbolAddress((void**)&vh,  g_v_h);
    cudaGetSymbolAddress((void**)&vl,  g_v_l);

    cudaFuncSetAttribute(gemm_mma_kernel,
                         cudaFuncAttributeMaxDynamicSharedMemorySize,
                         NSTAGE * STG_B);
    cudaFuncSetAttribute(flash_mma_kernel,
                         cudaFuncAttributeMaxDynamicSharedMemorySize,
                         FLASH_SMEM);

    // 0a. split x -> bf16 hi/lo
    {
        size_t n = (size_t)M1 * K1;
        split_kernel<<<(unsigned)(n / 4 / 256), 256>>>(x, xh, xl, n);
    }
    // 0b. transpose+split weights
    transpose_split_kernel<<<dim3(N1 / 32, K1 / 32), dim3(32, 8)>>>(Wqkv, wqh, wql, K1, N1);
    transpose_split_kernel<<<dim3(CC / 32, K1 / 32), dim3(32, 8)>>>(Wout, woh, wol, K1, CC);

    // 1. QKV projection (mma.sync bf16x3)
    gemm_mma_kernel<<<dim3(N1 / GBN, M1 / GBM), 256, NSTAGE * STG_B>>>(
        xh, xl, wqh, wql, qkv, M1, N1, K1);

    // 2. RoPE + split to bf16 hi/lo [B,H,T,hd]
    {
        size_t total = (size_t)BB * TT * CC;
        rope_split_kernel<<<(unsigned)((total + 255) / 256), 256>>>(
            qkv, qh, ql, kh, kl, vh, vl);
    }

    // 3. Flash attention on tensor cores (writes yh/yl directly)
    flash_mma_kernel<<<dim3(TT / AQ2, BB * HH), 256, FLASH_SMEM>>>(
        qh, ql, kh, kl, vh, vl, yh, yl);

    // 4. Output projection (mma.sync bf16x3)
    gemm_mma_kernel<<<dim3(CC / GBN, M1 / GBM), 256, NSTAGE * STG_B>>>(
        yh, yl, woh, wol, out, M1, CC, K1);
}

// round 8
// speedup vs baseline: 1.3735x; 1.3735x over previous
#include <cuda_runtime.h>
#include <cuda_bf16.h>
#include <cuda_fp16.h>
#include <math.h>
#include <stdint.h>

// Problem dims
#define BB 16
#define TT 512
#define CC 2048
#define HH 16
#define HD 128
#define ROPE_D 16
#define M1 (BB*TT)        // 8192
#define N1 (3*CC)         // 6144
#define K1 CC             // 2048

// ---------------- scratch (device globals; no allocation allowed) ----------
__device__ float g_qkv[(size_t)M1 * N1];                 // [8192,6144]

// fp16 hi/lo for GEMM operands
__device__ __half g_xh[(size_t)M1 * K1];
__device__ __half g_xl[(size_t)M1 * K1];
__device__ __half g_wqh[(size_t)N1 * K1];                // Wqkv^T [6144,2048] fp16
__device__ __half g_woh[(size_t)CC * CC];                // Wout^T [2048,2048] fp16
__device__ __half g_yh[(size_t)M1 * CC];
__device__ __half g_yl[(size_t)M1 * CC];
// q/k/v hi/lo (bf16, attention keeps bf16x3), [B*H, T, 128]
__device__ __nv_bfloat16 g_q_h[(size_t)BB*HH*TT*HD];
__device__ __nv_bfloat16 g_q_l[(size_t)BB*HH*TT*HD];
__device__ __nv_bfloat16 g_k_h[(size_t)BB*HH*TT*HD];
__device__ __nv_bfloat16 g_k_l[(size_t)BB*HH*TT*HD];
__device__ __nv_bfloat16 g_v_h[(size_t)BB*HH*TT*HD];
__device__ __nv_bfloat16 g_v_l[(size_t)BB*HH*TT*HD];

// ======================= PTX helpers (baseline ISA only) ===================
__device__ __forceinline__ uint32_t smem_u32(const void* p) {
    uint32_t a;
    asm("{ .reg .u64 t; cvta.to.shared.u64 t, %1; cvt.u32.u64 %0, t; }"
        : "=r"(a) : "l"(p));
    return a;
}
__device__ __forceinline__ void cpasync16(uint32_t dst, const void* src) {
    asm volatile("cp.async.cg.shared.global [%0], [%1], 16;"
                 :: "r"(dst), "l"(src) : "memory");
}
__device__ __forceinline__ void cpasync_commit() {
    asm volatile("cp.async.commit_group;" ::: "memory");
}
__device__ __forceinline__ void cpasync_wait1() {
    asm volatile("cp.async.wait_group 1;" ::: "memory");
}
__device__ __forceinline__ void ldsm_x4(uint32_t& r0, uint32_t& r1,
                                        uint32_t& r2, uint32_t& r3, uint32_t a) {
    asm volatile("ldmatrix.sync.aligned.m8n8.x4.shared.b16 {%0,%1,%2,%3}, [%4];"
                 : "=r"(r0), "=r"(r1), "=r"(r2), "=r"(r3) : "r"(a));
}
__device__ __forceinline__ void ldsm_x4_t(uint32_t& r0, uint32_t& r1,
                                          uint32_t& r2, uint32_t& r3, uint32_t a) {
    asm volatile("ldmatrix.sync.aligned.m8n8.x4.trans.shared.b16 {%0,%1,%2,%3}, [%4];"
                 : "=r"(r0), "=r"(r1), "=r"(r2), "=r"(r3) : "r"(a));
}
// bf16 mma (attention)
__device__ __forceinline__ void mma16816b(float* d, const uint32_t* a,
                                          const uint32_t* b) {
    asm volatile(
        "mma.sync.aligned.m16n8k16.row.col.f32.bf16.bf16.f32 "
        "{%0,%1,%2,%3}, {%4,%5,%6,%7}, {%8,%9}, {%0,%1,%2,%3};"
        : "+f"(d[0]), "+f"(d[1]), "+f"(d[2]), "+f"(d[3])
        : "r"(a[0]), "r"(a[1]), "r"(a[2]), "r"(a[3]), "r"(b[0]), "r"(b[1]));
}
// fp16 mma (GEMMs)
__device__ __forceinline__ void mma16816f(float* d, const uint32_t* a,
                                          const uint32_t* b) {
    asm volatile(
        "mma.sync.aligned.m16n8k16.row.col.f32.f16.f16.f32 "
        "{%0,%1,%2,%3}, {%4,%5,%6,%7}, {%8,%9}, {%0,%1,%2,%3};"
        : "+f"(d[0]), "+f"(d[1]), "+f"(d[2]), "+f"(d[3])
        : "r"(a[0]), "r"(a[1]), "r"(a[2]), "r"(a[3]), "r"(b[0]), "r"(b[1]));
}
__device__ __forceinline__ uint32_t packbf(float a, float b) {
    __nv_bfloat162 t = __floats2bfloat162_rn(a, b);
    return *reinterpret_cast<uint32_t*>(&t);
}
// bf16 hi/lo split (attention P fragments)
__device__ __forceinline__ void split2(float a, float b, uint32_t& hi, uint32_t& lo) {
    float ah = __bfloat162float(__float2bfloat16(a));
    float bh = __bfloat162float(__float2bfloat16(b));
    hi = packbf(ah, bh);
    lo = packbf(a - ah, b - bh);
}
// fp16 hi/lo split of two floats into packed half2 words
__device__ __forceinline__ void split2h(float a, float b, uint32_t& hi, uint32_t& lo) {
    __half ah = __float2half_rn(a), bh = __float2half_rn(b);
    __half al = __float2half_rn(a - __half2float(ah));
    __half bl = __float2half_rn(b - __half2float(bh));
    __half2 h2 = __halves2half2(ah, bh);
    __half2 l2 = __halves2half2(al, bl);
    hi = *reinterpret_cast<uint32_t*>(&h2);
    lo = *reinterpret_cast<uint32_t*>(&l2);
}

// ======================= mma.sync fp16x2 GEMM ==============================
// C[M,N] (f32) = (Ah+Al)[M,K] fp16 @ (Bh [N,K] fp16)^T  -- 2 MMA products.
#define GBM 128
#define GBN 128
#define GBK 32
#define TILE_B (128 * 64)            // 8192 B per tile
#define STG_B  (3 * TILE_B)          // Ah, Al, Bh = 24576
#define NSTAGE 3

// conflict-free smem offset: row stride 64B, chunk (16B) XOR'd with (row>>1)&3
__device__ __forceinline__ uint32_t swz(int row, int chunk) {
    return (uint32_t)((row << 6) + ((chunk ^ ((row >> 1) & 3)) << 4));
}

__device__ __forceinline__ void g2s_stage(
    uint32_t sbase,
    const __half* __restrict__ Ah, const __half* __restrict__ Al,
    const __half* __restrict__ Bh,
    int m0, int n0, int k0, int K, int tid)
{
#pragma unroll
    for (int i = 0; i < 2; i++) {
        int s = tid + i * 256;               // 0..511
        int r = s >> 2, c = s & 3;           // row 0..127, 16B chunk 0..3
        uint32_t so = swz(r, c);
        size_t ga = (size_t)(m0 + r) * K + k0 + c * 8;
        size_t gb = (size_t)(n0 + r) * K + k0 + c * 8;
        cpasync16(sbase + 0 * TILE_B + so, Ah + ga);
        cpasync16(sbase + 1 * TILE_B + so, Al + ga);
        cpasync16(sbase + 2 * TILE_B + so, Bh + gb);
    }
}

__global__ __launch_bounds__(256, 2)
void gemm_mma_kernel(const __half* __restrict__ Ah,
                     const __half* __restrict__ Al,
                     const __half* __restrict__ Bh,
                     float* __restrict__ C, int M, int N, int K)
{
    extern __shared__ char sm_raw[];
    const uint32_t smbase = smem_u32(sm_raw);
    const int tid = threadIdx.x, wid = tid >> 5, lane = tid & 31;
    const int wm = (wid >> 2) * 64;
    const int wn = (wid & 3) * 32;
    const int m0 = blockIdx.y * GBM;
    const int n0 = blockIdx.x * GBN;
    const int lrow = lane & 15;
    const int lch  = (lane >> 4) & 1;

    float acc[4][4][4];
#pragma unroll
    for (int a = 0; a < 4; a++)
#pragma unroll
        for (int b = 0; b < 4; b++)
#pragma unroll
            for (int c = 0; c < 4; c++) acc[a][b][c] = 0.0f;

    g2s_stage(smbase + 0 * STG_B, Ah, Al, Bh, m0, n0, 0, K, tid);
    cpasync_commit();
    g2s_stage(smbase + 1 * STG_B, Ah, Al, Bh, m0, n0, GBK, K, tid);
    cpasync_commit();

    const int niter = K / GBK;               // 64
    int stage = 0, nstage = 2;
    for (int it = 0; it < niter; ++it) {
        cpasync_wait1();
        __syncthreads();

        if (it + 2 < niter)
            g2s_stage(smbase + nstage * STG_B, Ah, Al, Bh,
                      m0, n0, (it + 2) * GBK, K, tid);
        cpasync_commit();
        if (++nstage == NSTAGE) nstage = 0;

        const uint32_t sb = smbase + stage * STG_B;
        if (++stage == NSTAGE) stage = 0;

#pragma unroll
        for (int kb = 0; kb < 2; ++kb) {
            const int chunk = kb * 2 + lch;
            uint32_t ah[4][4], al[4][4];
#pragma unroll
            for (int mf = 0; mf < 4; ++mf) {
                uint32_t off = swz(wm + mf * 16 + lrow, chunk);
                ldsm_x4(ah[mf][0], ah[mf][1], ah[mf][2], ah[mf][3],
                        sb + 0 * TILE_B + off);
                ldsm_x4(al[mf][0], al[mf][1], al[mf][2], al[mf][3],
                        sb + 1 * TILE_B + off);
            }
            uint32_t bh[4][2];
#pragma unroll
            for (int np = 0; np < 2; ++np) {
                uint32_t off = swz(wn + np * 16 + lrow, chunk);
                uint32_t r0, r1, r2, r3;
                ldsm_x4(r0, r1, r2, r3, sb + 2 * TILE_B + off);
                bh[np*2][0] = r0; bh[np*2][1] = r2;
                bh[np*2+1][0] = r1; bh[np*2+1][1] = r3;
            }
#pragma unroll
            for (int mf = 0; mf < 4; ++mf)
#pragma unroll
                for (int nf = 0; nf < 4; ++nf) {
                    mma16816f(acc[mf][nf], ah[mf], bh[nf]);
                    mma16816f(acc[mf][nf], al[mf], bh[nf]);
                }
        }
    }

    // epilogue
    const int l4 = lane >> 2, l2 = (lane & 3) * 2;
#pragma unroll
    for (int mf = 0; mf < 4; ++mf) {
        int r0 = m0 + wm + mf * 16 + l4;
#pragma unroll
        for (int nf = 0; nf < 4; ++nf) {
            int cx = n0 + wn + nf * 8 + l2;
            *(float2*)&C[(size_t)r0 * N + cx] =
                make_float2(acc[mf][nf][0], acc[mf][nf][1]);
            *(float2*)&C[(size_t)(r0 + 8) * N + cx] =
                make_float2(acc[mf][nf][2], acc[mf][nf][3]);
        }
    }
}

// ======================= conversion kernels ================================
// f32 -> fp16 hi/lo
__global__ __launch_bounds__(256)
void split_kernel(const float* __restrict__ in, __half* __restrict__ hi,
                  __half* __restrict__ lo, size_t n)
{
    size_t i = ((size_t)blockIdx.x * blockDim.x + threadIdx.x) * 4;
    if (i >= n) return;
    float4 x = *(const float4*)(in + i);
    uint32_t h0, l0, h1, l1;
    split2h(x.x, x.y, h0, l0);
    split2h(x.z, x.w, h1, l1);
    uint32_t* hp = (uint32_t*)(hi + i);
    uint32_t* lp = (uint32_t*)(lo + i);
    hp[0] = h0; hp[1] = h1;
    lp[0] = l0; lp[1] = l1;
}

// W [K,N] f32 -> Th [N,K] fp16 (hi only)
__global__ __launch_bounds__(256)
void transpose_split_kernel(const float* __restrict__ W,
                            __half* __restrict__ Th, int K, int N)
{
    __shared__ float tile[32][33];
    int n0 = blockIdx.x * 32, k0 = blockIdx.y * 32;
    int tx = threadIdx.x, ty = threadIdx.y;   // 32 x 8
#pragma unroll
    for (int i = 0; i < 32; i += 8)
        tile[ty + i][tx] = W[(size_t)(k0 + ty + i) * N + n0 + tx];
    __syncthreads();
#pragma unroll
    for (int i = 0; i < 32; i += 8) {
        float x = tile[tx][ty + i];
        size_t o = (size_t)(n0 + ty + i) * K + k0 + tx;
        Th[o] = __float2half_rn(x);
    }
}

// ---------------- RoPE + split to bf16 hi/lo (attention inputs) ------------
__global__ __launch_bounds__(256)
void rope_split_kernel(const float* __restrict__ qkv,
                       __nv_bfloat16* __restrict__ qh, __nv_bfloat16* __restrict__ ql,
                       __nv_bfloat16* __restrict__ kh, __nv_bfloat16* __restrict__ kl,
                       __nv_bfloat16* __restrict__ vh, __nv_bfloat16* __restrict__ vl)
{
    size_t idx = (size_t)blockIdx.x * blockDim.x + threadIdx.x;
    if (idx >= (size_t)BB * TT * CC) return;
    int d = idx & (HD - 1);
    int h = (idx >> 7) & (HH - 1);
    int t = (idx >> 11) & (TT - 1);
    int b = idx >> 20;

    size_t srow = (size_t)(b * TT + t) * N1;
    size_t base = srow + h * HD + d;

    float qv = qkv[base];
    float kv = qkv[base + CC];
    float vv = qkv[base + 2 * CC];

    if (d < ROPE_D) {
        int j = (d < 8) ? d : d - 8;
        float freq = (float)t * powf(10000.0f, -(float)j / 8.0f);
        float c, s;
        sincosf(freq, &s, &c);
        if (d < 8) {
            float qo = qkv[base + 8];
            float ko = qkv[base + CC + 8];
            qv = qv * c - qo * s;
            kv = kv * c - ko * s;
        } else {
            float qo = qkv[base - 8];
            float ko = qkv[base + CC - 8];
            qv = qv * c + qo * s;
            kv = kv * c + ko * s;
        }
    }
    qv *= 0.08838834764831845f;   // fold 1/sqrt(128) into Q

    size_t dst = (((size_t)(b * HH + h)) * TT + t) * HD + d;
    float qhi = __bfloat162float(__float2bfloat16(qv));
    qh[dst] = __float2bfloat16(qv);
    ql[dst] = __float2bfloat16(qv - qhi);
    float khi = __bfloat162float(__float2bfloat16(kv));
    kh[dst] = __float2bfloat16(kv);
    kl[dst] = __float2bfloat16(kv - khi);
    float vhi = __bfloat162float(__float2bfloat16(vv));
    vh[dst] = __float2bfloat16(vv);
    vl[dst] = __float2bfloat16(vv - vhi);
}

// ---------------- Flash attention (mma.sync bf16x3, causal) ----------------
// CTA: 128 q-rows (8 warps x 16), kv tile 64, double-buffered KV pipeline.
#define AQ2 128
#define AKV 64
#define Q_TILE_B  (128 * 256)          // 32768 per Q array (hi or lo)
#define KV_TILE_B (64 * 256)           // 16384 per KV array
#define KV_STG_B  (4 * KV_TILE_B)      // Kh,Kl,Vh,Vl = 65536
#define FLASH_SMEM (2 * Q_TILE_B + 2 * KV_STG_B)   // 196608

__device__ __forceinline__ uint32_t aswz(int row, int chunk) {
    return (uint32_t)((row << 8) + ((chunk ^ (row & 7)) << 4));
}

__device__ __forceinline__ void kv_stage_load(
    uint32_t skv,
    const __nv_bfloat16* __restrict__ Kh, const __nv_bfloat16* __restrict__ Kl,
    const __nv_bfloat16* __restrict__ Vh, const __nv_bfloat16* __restrict__ Vl,
    size_t kg, int tid)
{
#pragma unroll
    for (int i = 0; i < 4; i++) {
        int s = tid + i * 256;            // 0..1023
        int r = s >> 4, c = s & 15;       // 64 rows x 16 chunks
        uint32_t so = aswz(r, c);
        size_t go = kg + (size_t)r * HD + c * 8;
        cpasync16(skv + 0 * KV_TILE_B + so, Kh + go);
        cpasync16(skv + 1 * KV_TILE_B + so, Kl + go);
        cpasync16(skv + 2 * KV_TILE_B + so, Vh + go);
        cpasync16(skv + 3 * KV_TILE_B + so, Vl + go);
    }
}

__global__ __launch_bounds__(256)
void flash_mma_kernel(const __nv_bfloat16* __restrict__ Qh, const __nv_bfloat16* __restrict__ Ql,
                      const __nv_bfloat16* __restrict__ Kh, const __nv_bfloat16* __restrict__ Kl,
                      const __nv_bfloat16* __restrict__ Vh, const __nv_bfloat16* __restrict__ Vl,
                      __half* __restrict__ Yh, __half* __restrict__ Yl)
{
    extern __shared__ char smraw[];
    const uint32_t sbse = smem_u32(smraw);
    const uint32_t sQh = sbse, sQl = sbse + Q_TILE_B;
    const uint32_t sKV0 = sbse + 2 * Q_TILE_B;

    const int tid = threadIdx.x, lane = tid & 31, wid = tid >> 5;
    const int qt = blockIdx.x, bhid = blockIdx.y;
    const int bb = bhid >> 4, hh = bhid & 15;
    const int q0 = qt * AQ2;
    const int l4 = lane >> 2, l2 = lane & 3;
    const int lrow = lane & 15, lch = lane >> 4;
    const int wq = wid * 16;                 // warp q-row base: 0..112

    const int jtmax = 2 * qt + 1;            // kv tiles 0..jtmax

    // G0: Q tile + KV stage 0
    const size_t qg = ((size_t)bhid * TT + q0) * HD;
#pragma unroll
    for (int i = 0; i < 8; i++) {
        int s = tid + i * 256;            // 0..2047
        int r = s >> 4, c = s & 15;       // 128 rows x 16 chunks
        uint32_t so = aswz(r, c);
        size_t go = qg + (size_t)r * HD + c * 8;
        cpasync16(sQh + so, Qh + go);
        cpasync16(sQl + so, Ql + go);
    }
    const size_t kvbase = (size_t)bhid * TT * HD;
    kv_stage_load(sKV0, Kh, Kl, Vh, Vl, kvbase, tid);
    cpasync_commit();
    kv_stage_load(sKV0 + KV_STG_B, Kh, Kl, Vh, Vl, kvbase + (size_t)AKV * HD, tid);
    cpasync_commit();

    float m0 = -1e30f, m1 = -1e30f, l0 = 0.0f, l1 = 0.0f;
    float oacc[16][4];
#pragma unroll
    for (int i = 0; i < 16; i++)
#pragma unroll
        for (int j = 0; j < 4; j++) oacc[i][j] = 0.0f;

    for (int jt = 0; jt <= jtmax; ++jt) {
        cpasync_wait1();                 // stage jt resident (one group pending)
        __syncthreads();

        const uint32_t skv = sKV0 + (jt & 1) * KV_STG_B;
        const uint32_t sk_h = skv, sk_l = skv + KV_TILE_B;
        const uint32_t sv_h = skv + 2 * KV_TILE_B, sv_l = skv + 3 * KV_TILE_B;

        // ---- S = Q K^T (pre-scaled Q; fp32 acc; bf16x3) ----
        float sacc[8][4];
#pragma unroll
        for (int i = 0; i < 8; i++)
#pragma unroll
            for (int j = 0; j < 4; j++) sacc[i][j] = 0.0f;

#pragma unroll
        for (int kb = 0; kb < 8; ++kb) {
            const int chunk = kb * 2 + lch;
            const uint32_t qa = aswz(wq + lrow, chunk);
            uint32_t ah[4], al[4];
            ldsm_x4(ah[0], ah[1], ah[2], ah[3], sQh + qa);
            ldsm_x4(al[0], al[1], al[2], al[3], sQl + qa);
#pragma unroll
            for (int np = 0; np < 4; ++np) {
                const uint32_t ka = aswz(np * 16 + lrow, chunk);
                uint32_t r0, r1, r2, r3;
                ldsm_x4(r0, r1, r2, r3, sk_h + ka);
                uint32_t b0[2] = {r0, r2}, b1[2] = {r1, r3};
                ldsm_x4(r0, r1, r2, r3, sk_l + ka);
                uint32_t c0[2] = {r0, r2}, c1[2] = {r1, r3};
                mma16816b(sacc[np*2],   ah, b0);
                mma16816b(sacc[np*2],   ah, c0);
                mma16816b(sacc[np*2],   al, b0);
                mma16816b(sacc[np*2+1], ah, b1);
                mma16816b(sacc[np*2+1], ah, c1);
                mma16816b(sacc[np*2+1], al, b1);
            }
        }

        // ---- causal mask (diagonal-region tiles) ----
        if (jt >= 2 * qt) {
            const int r0g = q0 + wq + l4, r1g = r0g + 8;
#pragma unroll
            for (int nf = 0; nf < 8; ++nf) {
                int c0 = jt * AKV + nf * 8 + 2 * l2;
                if (c0     > r0g) sacc[nf][0] = -1e30f;
                if (c0 + 1 > r0g) sacc[nf][1] = -1e30f;
                if (c0     > r1g) sacc[nf][2] = -1e30f;
                if (c0 + 1 > r1g) sacc[nf][3] = -1e30f;
            }
        }

        // ---- online softmax ----
        float rx0 = -1e30f, rx1 = -1e30f;
#pragma unroll
        for (int nf = 0; nf < 8; ++nf) {
            rx0 = fmaxf(rx0, fmaxf(sacc[nf][0], sacc[nf][1]));
            rx1 = fmaxf(rx1, fmaxf(sacc[nf][2], sacc[nf][3]));
        }
#pragma unroll
        for (int off = 2; off >= 1; off >>= 1) {
            rx0 = fmaxf(rx0, __shfl_xor_sync(0xffffffffu, rx0, off));
            rx1 = fmaxf(rx1, __shfl_xor_sync(0xffffffffu, rx1, off));
        }
        float nm0 = fmaxf(m0, rx0), nm1 = fmaxf(m1, rx1);
        float a0 = __expf(m0 - nm0), a1 = __expf(m1 - nm1);
        m0 = nm0; m1 = nm1;
        float s0 = 0.0f, s1 = 0.0f;
#pragma unroll
        for (int nf = 0; nf < 8; ++nf) {
            sacc[nf][0] = __expf(sacc[nf][0] - nm0); s0 += sacc[nf][0];
            sacc[nf][1] = __expf(sacc[nf][1] - nm0); s0 += sacc[nf][1];
            sacc[nf][2] = __expf(sacc[nf][2] - nm1); s1 += sacc[nf][2];
            sacc[nf][3] = __expf(sacc[nf][3] - nm1); s1 += sacc[nf][3];
        }
#pragma unroll
        for (int off = 2; off >= 1; off >>= 1) {
            s0 += __shfl_xor_sync(0xffffffffu, s0, off);
            s1 += __shfl_xor_sync(0xffffffffu, s1, off);
        }
        l0 = l0 * a0 + s0;
        l1 = l1 * a1 + s1;
#pragma unroll
        for (int nt = 0; nt < 16; ++nt) {
            oacc[nt][0] *= a0; oacc[nt][1] *= a0;
            oacc[nt][2] *= a1; oacc[nt][3] *= a1;
        }

        // ---- O += P V ----
#pragma unroll
        for (int kt = 0; kt < 4; ++kt) {
            uint32_t ph[4], pl[4];
            split2(sacc[2*kt][0],   sacc[2*kt][1],   ph[0], pl[0]);
            split2(sacc[2*kt][2],   sacc[2*kt][3],   ph[1], pl[1]);
            split2(sacc[2*kt+1][0], sacc[2*kt+1][1], ph[2], pl[2]);
            split2(sacc[2*kt+1][2], sacc[2*kt+1][3], ph[3], pl[3]);
#pragma unroll
            for (int nd = 0; nd < 8; ++nd) {
                const uint32_t va = aswz(kt * 16 + lrow, nd * 2 + lch);
                uint32_t h0, h1, h2, h3, x0, x1, x2, x3;
                ldsm_x4_t(h0, h1, h2, h3, sv_h + va);
                ldsm_x4_t(x0, x1, x2, x3, sv_l + va);
                uint32_t vb0[2] = {h0, h1}, vb1[2] = {h2, h3};
                uint32_t wb0[2] = {x0, x1}, wb1[2] = {x2, x3};
                mma16816b(oacc[nd*2],   ph, vb0);
                mma16816b(oacc[nd*2],   ph, wb0);
                mma16816b(oacc[nd*2],   pl, vb0);
                mma16816b(oacc[nd*2+1], ph, vb1);
                mma16816b(oacc[nd*2+1], ph, wb1);
                mma16816b(oacc[nd*2+1], pl, vb1);
            }
        }

        // refill the stage just consumed (stage jt&1) for tile jt+2
        __syncthreads();
        if (jt + 2 <= jtmax)
            kv_stage_load(sKV0 + (jt & 1) * KV_STG_B, Kh, Kl, Vh, Vl,
                          kvbase + (size_t)(jt + 2) * AKV * HD, tid);
        cpasync_commit();                // one group per iter (may be empty)
    }

    // ---- epilogue: normalize, fp16 hi/lo split, write Yh/Yl [B,T,C] ----
    const float il0 = 1.0f / l0, il1 = 1.0f / l1;
    const int r0g = q0 + wq + l4, r1g = r0g + 8;
#pragma unroll
    for (int nt = 0; nt < 16; ++nt) {
        int col = hh * HD + nt * 8 + 2 * l2;
        size_t o0 = ((size_t)bb * TT + r0g) * CC + col;
        size_t o1 = ((size_t)bb * TT + r1g) * CC + col;
        uint32_t h, l;
        split2h(oacc[nt][0] * il0, oacc[nt][1] * il0, h, l);
        *reinterpret_cast<uint32_t*>(Yh + o0) = h;
        *reinterpret_cast<uint32_t*>(Yl + o0) = l;
        split2h(oacc[nt][2] * il1, oacc[nt][3] * il1, h, l);
        *reinterpret_cast<uint32_t*>(Yh + o1) = h;
        *reinterpret_cast<uint32_t*>(Yl + o1) = l;
    }
}

// ---------------- launch ----------------------------------------------------
extern "C" void kernel_launch(void* const* d_in, const int* in_sizes, int n_in,
                              void* d_out, int out_size)
{
    const float* x    = (const float*)d_in[0];
    const float* Wqkv = (const float*)d_in[1];
    const float* Wout = (const float*)d_in[2];
    float* out = (float*)d_out;

    float* qkv;
    cudaGetSymbolAddress((void**)&qkv, g_qkv);
    __half *xh, *xl, *wqh, *woh, *yh, *yl;
    __nv_bfloat16 *qh, *ql, *kh, *kl, *vh, *vl;
    cudaGetSymbolAddress((void**)&xh,  g_xh);
    cudaGetSymbolAddress((void**)&xl,  g_xl);
    cudaGetSymbolAddress((void**)&wqh, g_wqh);
    cudaGetSymbolAddress((void**)&woh, g_woh);
    cudaGetSymbolAddress((void**)&yh,  g_yh);
    cudaGetSymbolAddress((void**)&yl,  g_yl);
    cudaGetSymbolAddress((void**)&qh,  g_q_h);
    cudaGetSymbolAddress((void**)&ql,  g_q_l);
    cudaGetSymbolAddress((void**)&kh,  g_k_h);
    cudaGetSymbolAddress((void**)&kl,  g_k_l);
    cudaGetSymbolAddress((void**)&vh,  g_v_h);
    cudaGetSymbolAddress((void**)&vl,  g_v_l);

    cudaFuncSetAttribute(gemm_mma_kernel,
                         cudaFuncAttributeMaxDynamicSharedMemorySize,
                         NSTAGE * STG_B);
    cudaFuncSetAttribute(flash_mma_kernel,
                         cudaFuncAttributeMaxDynamicSharedMemorySize,
                         FLASH_SMEM);

    // 0a. split x -> fp16 hi/lo
    {
        size_t n = (size_t)M1 * K1;
        split_kernel<<<(unsigned)(n / 4 / 256), 256>>>(x, xh, xl, n);
    }
    // 0b. transpose weights -> fp16 (hi only)
    transpose_split_kernel<<<dim3(N1 / 32, K1 / 32), dim3(32, 8)>>>(Wqkv, wqh, K1, N1);
    transpose_split_kernel<<<dim3(CC / 32, K1 / 32), dim3(32, 8)>>>(Wout, woh, K1, CC);

    // 1. QKV projection (mma.sync fp16x2)
    gemm_mma_kernel<<<dim3(N1 / GBN, M1 / GBM), 256, NSTAGE * STG_B>>>(
        xh, xl, wqh, qkv, M1, N1, K1);

    // 2. RoPE + split to bf16 hi/lo [B,H,T,hd]
    {
        size_t total = (size_t)BB * TT * CC;
        rope_split_kernel<<<(unsigned)((total + 255) / 256), 256>>>(
            qkv, qh, ql, kh, kl, vh, vl);
    }

    // 3. Flash attention on tensor cores (writes yh/yl fp16 directly)
    flash_mma_kernel<<<dim3(TT / AQ2, BB * HH), 256, FLASH_SMEM>>>(
        qh, ql, kh, kl, vh, vl, yh, yl);

    // 4. Output projection (mma.sync fp16x2)
    gemm_mma_kernel<<<dim3(CC / GBN, M1 / GBM), 256, NSTAGE * STG_B>>>(
        yh, yl, woh, out, M1, CC, K1);
}

// round 9
// speedup vs baseline: 1.4122x; 1.0281x over previous
#include <cuda_runtime.h>
#include <cuda_fp16.h>
#include <math.h>
#include <stdint.h>

// Problem dims
#define BB 16
#define TT 512
#define CC 2048
#define HH 16
#define HD 128
#define ROPE_D 16
#define M1 (BB*TT)        // 8192
#define N1 (3*CC)         // 6144
#define K1 CC             // 2048

// ---------------- scratch (device globals; no allocation allowed) ----------
__device__ float g_qkv[(size_t)M1 * N1];                 // [8192,6144]

// fp16 hi/lo for GEMM operands
__device__ __half g_xh[(size_t)M1 * K1];
__device__ __half g_xl[(size_t)M1 * K1];
__device__ __half g_wqh[(size_t)N1 * K1];                // Wqkv^T [6144,2048] fp16
__device__ __half g_woh[(size_t)CC * CC];                // Wout^T [2048,2048] fp16
__device__ __half g_yh[(size_t)M1 * CC];
__device__ __half g_yl[(size_t)M1 * CC];
// attention operands (fp16), [B*H, T, 128]: Q hi/lo exact, K/V hi only
__device__ __half g_q_h[(size_t)BB*HH*TT*HD];
__device__ __half g_q_l[(size_t)BB*HH*TT*HD];
__device__ __half g_k_h[(size_t)BB*HH*TT*HD];
__device__ __half g_v_h[(size_t)BB*HH*TT*HD];

// ======================= PTX helpers (baseline ISA only) ===================
__device__ __forceinline__ uint32_t smem_u32(const void* p) {
    uint32_t a;
    asm("{ .reg .u64 t; cvta.to.shared.u64 t, %1; cvt.u32.u64 %0, t; }"
        : "=r"(a) : "l"(p));
    return a;
}
__device__ __forceinline__ void cpasync16(uint32_t dst, const void* src) {
    asm volatile("cp.async.cg.shared.global [%0], [%1], 16;"
                 :: "r"(dst), "l"(src) : "memory");
}
__device__ __forceinline__ void cpasync_commit() {
    asm volatile("cp.async.commit_group;" ::: "memory");
}
__device__ __forceinline__ void cpasync_wait1() {
    asm volatile("cp.async.wait_group 1;" ::: "memory");
}
__device__ __forceinline__ void cpasync_wait2() {
    asm volatile("cp.async.wait_group 2;" ::: "memory");
}
__device__ __forceinline__ void ldsm_x4(uint32_t& r0, uint32_t& r1,
                                        uint32_t& r2, uint32_t& r3, uint32_t a) {
    asm volatile("ldmatrix.sync.aligned.m8n8.x4.shared.b16 {%0,%1,%2,%3}, [%4];"
                 : "=r"(r0), "=r"(r1), "=r"(r2), "=r"(r3) : "r"(a));
}
__device__ __forceinline__ void ldsm_x4_t(uint32_t& r0, uint32_t& r1,
                                          uint32_t& r2, uint32_t& r3, uint32_t a) {
    asm volatile("ldmatrix.sync.aligned.m8n8.x4.trans.shared.b16 {%0,%1,%2,%3}, [%4];"
                 : "=r"(r0), "=r"(r1), "=r"(r2), "=r"(r3) : "r"(a));
}
// fp16 mma, fp32 accumulate
__device__ __forceinline__ void mma16816f(float* d, const uint32_t* a,
                                          const uint32_t* b) {
    asm volatile(
        "mma.sync.aligned.m16n8k16.row.col.f32.f16.f16.f32 "
        "{%0,%1,%2,%3}, {%4,%5,%6,%7}, {%8,%9}, {%0,%1,%2,%3};"
        : "+f"(d[0]), "+f"(d[1]), "+f"(d[2]), "+f"(d[3])
        : "r"(a[0]), "r"(a[1]), "r"(a[2]), "r"(a[3]), "r"(b[0]), "r"(b[1]));
}
// fp16 hi/lo split of two floats into packed half2 words
__device__ __forceinline__ void split2h(float a, float b, uint32_t& hi, uint32_t& lo) {
    __half ah = __float2half_rn(a), bh = __float2half_rn(b);
    __half al = __float2half_rn(a - __half2float(ah));
    __half bl = __float2half_rn(b - __half2float(bh));
    __half2 h2 = __halves2half2(ah, bh);
    __half2 l2 = __halves2half2(al, bl);
    hi = *reinterpret_cast<uint32_t*>(&h2);
    lo = *reinterpret_cast<uint32_t*>(&l2);
}

// ======================= mma.sync fp16x2 GEMM ==============================
// C[M,N] (f32) = (Ah+Al)[M,K] fp16 @ (Bh [N,K] fp16)^T  -- 2 MMA products.
#define GBM 128
#define GBN 128
#define GBK 32
#define TILE_B (128 * 64)            // 8192 B per tile
#define STG_B  (3 * TILE_B)          // Ah, Al, Bh = 24576
#define NSTAGE 4

// conflict-free smem offset: row stride 64B, chunk (16B) XOR'd with (row>>1)&3
__device__ __forceinline__ uint32_t swz(int row, int chunk) {
    return (uint32_t)((row << 6) + ((chunk ^ ((row >> 1) & 3)) << 4));
}

__device__ __forceinline__ void g2s_stage(
    uint32_t sbase,
    const __half* __restrict__ Ah, const __half* __restrict__ Al,
    const __half* __restrict__ Bh,
    int m0, int n0, int k0, int K, int tid)
{
#pragma unroll
    for (int i = 0; i < 2; i++) {
        int s = tid + i * 256;               // 0..511
        int r = s >> 2, c = s & 3;           // row 0..127, 16B chunk 0..3
        uint32_t so = swz(r, c);
        size_t ga = (size_t)(m0 + r) * K + k0 + c * 8;
        size_t gb = (size_t)(n0 + r) * K + k0 + c * 8;
        cpasync16(sbase + 0 * TILE_B + so, Ah + ga);
        cpasync16(sbase + 1 * TILE_B + so, Al + ga);
        cpasync16(sbase + 2 * TILE_B + so, Bh + gb);
    }
}

__global__ __launch_bounds__(256, 2)
void gemm_mma_kernel(const __half* __restrict__ Ah,
                     const __half* __restrict__ Al,
                     const __half* __restrict__ Bh,
                     float* __restrict__ C, int M, int N, int K)
{
    extern __shared__ char sm_raw[];
    const uint32_t smbase = smem_u32(sm_raw);
    const int tid = threadIdx.x, wid = tid >> 5, lane = tid & 31;
    const int wm = (wid >> 2) * 64;
    const int wn = (wid & 3) * 32;
    const int m0 = blockIdx.y * GBM;
    const int n0 = blockIdx.x * GBN;
    const int lrow = lane & 15;
    const int lch  = (lane >> 4) & 1;

    float acc[4][4][4];
#pragma unroll
    for (int a = 0; a < 4; a++)
#pragma unroll
        for (int b = 0; b < 4; b++)
#pragma unroll
            for (int c = 0; c < 4; c++) acc[a][b][c] = 0.0f;

    // prologue: fill stages 0..2 (3 outstanding groups)
    g2s_stage(smbase + 0 * STG_B, Ah, Al, Bh, m0, n0, 0 * GBK, K, tid);
    cpasync_commit();
    g2s_stage(smbase + 1 * STG_B, Ah, Al, Bh, m0, n0, 1 * GBK, K, tid);
    cpasync_commit();
    g2s_stage(smbase + 2 * STG_B, Ah, Al, Bh, m0, n0, 2 * GBK, K, tid);
    cpasync_commit();

    const int niter = K / GBK;               // 64
    for (int it = 0; it < niter; ++it) {
        cpasync_wait2();                     // chunk `it` resident
        __syncthreads();

        // refill the stage freed last iter with chunk it+3 (before compute)
        if (it + 3 < niter)
            g2s_stage(smbase + ((it + 3) & 3) * STG_B, Ah, Al, Bh,
                      m0, n0, (it + 3) * GBK, K, tid);
        cpasync_commit();

        const uint32_t sb = smbase + (it & 3) * STG_B;

#pragma unroll
        for (int kb = 0; kb < 2; ++kb) {
            const int chunk = kb * 2 + lch;
            uint32_t ah[4][4], al[4][4];
#pragma unroll
            for (int mf = 0; mf < 4; ++mf) {
                uint32_t off = swz(wm + mf * 16 + lrow, chunk);
                ldsm_x4(ah[mf][0], ah[mf][1], ah[mf][2], ah[mf][3],
                        sb + 0 * TILE_B + off);
                ldsm_x4(al[mf][0], al[mf][1], al[mf][2], al[mf][3],
                        sb + 1 * TILE_B + off);
            }
            uint32_t bh[4][2];
#pragma unroll
            for (int np = 0; np < 2; ++np) {
                uint32_t off = swz(wn + np * 16 + lrow, chunk);
                uint32_t r0, r1, r2, r3;
                ldsm_x4(r0, r1, r2, r3, sb + 2 * TILE_B + off);
                bh[np*2][0] = r0; bh[np*2][1] = r2;
                bh[np*2+1][0] = r1; bh[np*2+1][1] = r3;
            }
#pragma unroll
            for (int mf = 0; mf < 4; ++mf)
#pragma unroll
                for (int nf = 0; nf < 4; ++nf) {
                    mma16816f(acc[mf][nf], ah[mf], bh[nf]);
                    mma16816f(acc[mf][nf], al[mf], bh[nf]);
                }
        }
        __syncthreads();   // stage (it&3) consumed; safe target for next refill
    }

    // epilogue
    const int l4 = lane >> 2, l2 = (lane & 3) * 2;
#pragma unroll
    for (int mf = 0; mf < 4; ++mf) {
        int r0 = m0 + wm + mf * 16 + l4;
#pragma unroll
        for (int nf = 0; nf < 4; ++nf) {
            int cx = n0 + wn + nf * 8 + l2;
            *(float2*)&C[(size_t)r0 * N + cx] =
                make_float2(acc[mf][nf][0], acc[mf][nf][1]);
            *(float2*)&C[(size_t)(r0 + 8) * N + cx] =
                make_float2(acc[mf][nf][2], acc[mf][nf][3]);
        }
    }
}

// ======================= conversion kernels ================================
// f32 -> fp16 hi/lo
__global__ __launch_bounds__(256)
void split_kernel(const float* __restrict__ in, __half* __restrict__ hi,
                  __half* __restrict__ lo, size_t n)
{
    size_t i = ((size_t)blockIdx.x * blockDim.x + threadIdx.x) * 4;
    if (i >= n) return;
    float4 x = *(const float4*)(in + i);
    uint32_t h0, l0, h1, l1;
    split2h(x.x, x.y, h0, l0);
    split2h(x.z, x.w, h1, l1);
    uint32_t* hp = (uint32_t*)(hi + i);
    uint32_t* lp = (uint32_t*)(lo + i);
    hp[0] = h0; hp[1] = h1;
    lp[0] = l0; lp[1] = l1;
}

// W [K,N] f32 -> Th [N,K] fp16 (hi only)
__global__ __launch_bounds__(256)
void transpose_split_kernel(const float* __restrict__ W,
                            __half* __restrict__ Th, int K, int N)
{
    __shared__ float tile[32][33];
    int n0 = blockIdx.x * 32, k0 = blockIdx.y * 32;
    int tx = threadIdx.x, ty = threadIdx.y;   // 32 x 8
#pragma unroll
    for (int i = 0; i < 32; i += 8)
        tile[ty + i][tx] = W[(size_t)(k0 + ty + i) * N + n0 + tx];
    __syncthreads();
#pragma unroll
    for (int i = 0; i < 32; i += 8) {
        float x = tile[tx][ty + i];
        size_t o = (size_t)(n0 + ty + i) * K + k0 + tx;
        Th[o] = __float2half_rn(x);
    }
}

// ---------------- RoPE + split to attention fp16 operands ------------------
// Q: hi/lo (exact); K, V: hi only (fp16-rounded).
__global__ __launch_bounds__(256)
void rope_split_kernel(const float* __restrict__ qkv,
                       __half* __restrict__ qh, __half* __restrict__ ql,
                       __half* __restrict__ kh, __half* __restrict__ vh)
{
    size_t idx = (size_t)blockIdx.x * blockDim.x + threadIdx.x;
    if (idx >= (size_t)BB * TT * CC) return;
    int d = idx & (HD - 1);
    int h = (idx >> 7) & (HH - 1);
    int t = (idx >> 11) & (TT - 1);
    int b = idx >> 20;

    size_t srow = (size_t)(b * TT + t) * N1;
    size_t base = srow + h * HD + d;

    float qv = qkv[base];
    float kv = qkv[base + CC];
    float vv = qkv[base + 2 * CC];

    if (d < ROPE_D) {
        int j = (d < 8) ? d : d - 8;
        float freq = (float)t * powf(10000.0f, -(float)j / 8.0f);
        float c, s;
        sincosf(freq, &s, &c);
        if (d < 8) {
            float qo = qkv[base + 8];
            float ko = qkv[base + CC + 8];
            qv = qv * c - qo * s;
            kv = kv * c - ko * s;
        } else {
            float qo = qkv[base - 8];
            float ko = qkv[base + CC - 8];
            qv = qv * c + qo * s;
            kv = kv * c + ko * s;
        }
    }
    qv *= 0.08838834764831845f;   // fold 1/sqrt(128) into Q

    size_t dst = (((size_t)(b * HH + h)) * TT + t) * HD + d;
    __half qhh = __float2half_rn(qv);
    qh[dst] = qhh;
    ql[dst] = __float2half_rn(qv - __half2float(qhh));
    kh[dst] = __float2half_rn(kv);
    vh[dst] = __float2half_rn(vv);
}

// ---------------- Flash attention (mma.sync fp16x2, causal) ----------------
// CTA: 128 q-rows (8 warps x 16), kv tile 64, double-buffered KV pipeline.
#define AQ2 128
#define AKV 64
#define Q_TILE_B  (128 * 256)          // 32768 per Q array (hi or lo)
#define KV_TILE_B (64 * 256)           // 16384 per KV array
#define KV_STG_B  (2 * KV_TILE_B)      // Kh, Vh = 32768
#define FLASH_SMEM (2 * Q_TILE_B + 2 * KV_STG_B)   // 131072

__device__ __forceinline__ uint32_t aswz(int row, int chunk) {
    return (uint32_t)((row << 8) + ((chunk ^ (row & 7)) << 4));
}

__device__ __forceinline__ void kv_stage_load(
    uint32_t skv,
    const __half* __restrict__ Kh, const __half* __restrict__ Vh,
    size_t kg, int tid)
{
#pragma unroll
    for (int i = 0; i < 4; i++) {
        int s = tid + i * 256;            // 0..1023
        int r = s >> 4, c = s & 15;       // 64 rows x 16 chunks
        uint32_t so = aswz(r, c);
        size_t go = kg + (size_t)r * HD + c * 8;
        cpasync16(skv + 0 * KV_TILE_B + so, Kh + go);
        cpasync16(skv + 1 * KV_TILE_B + so, Vh + go);
    }
}

__global__ __launch_bounds__(256)
void flash_mma_kernel(const __half* __restrict__ Qh, const __half* __restrict__ Ql,
                      const __half* __restrict__ Kh, const __half* __restrict__ Vh,
                      __half* __restrict__ Yh, __half* __restrict__ Yl)
{
    extern __shared__ char smraw[];
    const uint32_t sbse = smem_u32(smraw);
    const uint32_t sQh = sbse, sQl = sbse + Q_TILE_B;
    const uint32_t sKV0 = sbse + 2 * Q_TILE_B;

    const int tid = threadIdx.x, lane = tid & 31, wid = tid >> 5;
    const int qt = blockIdx.x, bhid = blockIdx.y;
    const int bb = bhid >> 4, hh = bhid & 15;
    const int q0 = qt * AQ2;
    const int l4 = lane >> 2, l2 = lane & 3;
    const int lrow = lane & 15, lch = lane >> 4;
    const int wq = wid * 16;                 // warp q-row base: 0..112

    const int jtmax = 2 * qt + 1;            // kv tiles 0..jtmax

    // G0: Q tile + KV stage 0
    const size_t qg = ((size_t)bhid * TT + q0) * HD;
#pragma unroll
    for (int i = 0; i < 8; i++) {
        int s = tid + i * 256;            // 0..2047
        int r = s >> 4, c = s & 15;       // 128 rows x 16 chunks
        uint32_t so = aswz(r, c);
        size_t go = qg + (size_t)r * HD + c * 8;
        cpasync16(sQh + so, Qh + go);
        cpasync16(sQl + so, Ql + go);
    }
    const size_t kvbase = (size_t)bhid * TT * HD;
    kv_stage_load(sKV0, Kh, Vh, kvbase, tid);
    cpasync_commit();
    kv_stage_load(sKV0 + KV_STG_B, Kh, Vh, kvbase + (size_t)AKV * HD, tid);
    cpasync_commit();

    float m0 = -1e30f, m1 = -1e30f, l0 = 0.0f, l1 = 0.0f;
    float oacc[16][4];
#pragma unroll
    for (int i = 0; i < 16; i++)
#pragma unroll
        for (int j = 0; j < 4; j++) oacc[i][j] = 0.0f;

    for (int jt = 0; jt <= jtmax; ++jt) {
        cpasync_wait1();                 // stage jt resident (one group pending)
        __syncthreads();

        const uint32_t skv = sKV0 + (jt & 1) * KV_STG_B;
        const uint32_t sk_h = skv, sv_h = skv + KV_TILE_B;

        // ---- S = Q K^T (pre-scaled Q; fp32 acc; fp16x2) ----
        float sacc[8][4];
#pragma unroll
        for (int i = 0; i < 8; i++)
#pragma unroll
            for (int j = 0; j < 4; j++) sacc[i][j] = 0.0f;

#pragma unroll
        for (int kb = 0; kb < 8; ++kb) {
            const int chunk = kb * 2 + lch;
            const uint32_t qa = aswz(wq + lrow, chunk);
            uint32_t ah[4], al[4];
            ldsm_x4(ah[0], ah[1], ah[2], ah[3], sQh + qa);
            ldsm_x4(al[0], al[1], al[2], al[3], sQl + qa);
#pragma unroll
            for (int np = 0; np < 4; ++np) {
                const uint32_t ka = aswz(np * 16 + lrow, chunk);
                uint32_t r0, r1, r2, r3;
                ldsm_x4(r0, r1, r2, r3, sk_h + ka);
                uint32_t b0[2] = {r0, r2}, b1[2] = {r1, r3};
                mma16816f(sacc[np*2],   ah, b0);
                mma16816f(sacc[np*2],   al, b0);
                mma16816f(sacc[np*2+1], ah, b1);
                mma16816f(sacc[np*2+1], al, b1);
            }
        }

        // ---- causal mask (diagonal-region tiles) ----
        if (jt >= 2 * qt) {
            const int r0g = q0 + wq + l4, r1g = r0g + 8;
#pragma unroll
            for (int nf = 0; nf < 8; ++nf) {
                int c0 = jt * AKV + nf * 8 + 2 * l2;
                if (c0     > r0g) sacc[nf][0] = -1e30f;
                if (c0 + 1 > r0g) sacc[nf][1] = -1e30f;
                if (c0     > r1g) sacc[nf][2] = -1e30f;
                if (c0 + 1 > r1g) sacc[nf][3] = -1e30f;
            }
        }

        // ---- online softmax ----
        float rx0 = -1e30f, rx1 = -1e30f;
#pragma unroll
        for (int nf = 0; nf < 8; ++nf) {
            rx0 = fmaxf(rx0, fmaxf(sacc[nf][0], sacc[nf][1]));
            rx1 = fmaxf(rx1, fmaxf(sacc[nf][2], sacc[nf][3]));
        }
#pragma unroll
        for (int off = 2; off >= 1; off >>= 1) {
            rx0 = fmaxf(rx0, __shfl_xor_sync(0xffffffffu, rx0, off));
            rx1 = fmaxf(rx1, __shfl_xor_sync(0xffffffffu, rx1, off));
        }
        float nm0 = fmaxf(m0, rx0), nm1 = fmaxf(m1, rx1);
        float a0 = __expf(m0 - nm0), a1 = __expf(m1 - nm1);
        m0 = nm0; m1 = nm1;
        float s0 = 0.0f, s1 = 0.0f;
#pragma unroll
        for (int nf = 0; nf < 8; ++nf) {
            sacc[nf][0] = __expf(sacc[nf][0] - nm0); s0 += sacc[nf][0];
            sacc[nf][1] = __expf(sacc[nf][1] - nm0); s0 += sacc[nf][1];
            sacc[nf][2] = __expf(sacc[nf][2] - nm1); s1 += sacc[nf][2];
            sacc[nf][3] = __expf(sacc[nf][3] - nm1); s1 += sacc[nf][3];
        }
#pragma unroll
        for (int off = 2; off >= 1; off >>= 1) {
            s0 += __shfl_xor_sync(0xffffffffu, s0, off);
            s1 += __shfl_xor_sync(0xffffffffu, s1, off);
        }
        l0 = l0 * a0 + s0;
        l1 = l1 * a1 + s1;
#pragma unroll
        for (int nt = 0; nt < 16; ++nt) {
            oacc[nt][0] *= a0; oacc[nt][1] *= a0;
            oacc[nt][2] *= a1; oacc[nt][3] *= a1;
        }

        // ---- O += P V (P exact via fp16 hi/lo; V fp16 hi) ----
#pragma unroll
        for (int kt = 0; kt < 4; ++kt) {
            uint32_t ph[4], pl[4];
            split2h(sacc[2*kt][0],   sacc[2*kt][1],   ph[0], pl[0]);
            split2h(sacc[2*kt][2],   sacc[2*kt][3],   ph[1], pl[1]);
            split2h(sacc[2*kt+1][0], sacc[2*kt+1][1], ph[2], pl[2]);
            split2h(sacc[2*kt+1][2], sacc[2*kt+1][3], ph[3], pl[3]);
#pragma unroll
            for (int nd = 0; nd < 8; ++nd) {
                const uint32_t va = aswz(kt * 16 + lrow, nd * 2 + lch);
                uint32_t h0, h1, h2, h3;
                ldsm_x4_t(h0, h1, h2, h3, sv_h + va);
                uint32_t vb0[2] = {h0, h1}, vb1[2] = {h2, h3};
                mma16816f(oacc[nd*2],   ph, vb0);
                mma16816f(oacc[nd*2],   pl, vb0);
                mma16816f(oacc[nd*2+1], ph, vb1);
                mma16816f(oacc[nd*2+1], pl, vb1);
            }
        }

        // refill the stage just consumed (stage jt&1) for tile jt+2
        __syncthreads();
        if (jt + 2 <= jtmax)
            kv_stage_load(sKV0 + (jt & 1) * KV_STG_B, Kh, Vh,
                          kvbase + (size_t)(jt + 2) * AKV * HD, tid);
        cpasync_commit();                // one group per iter (may be empty)
    }

    // ---- epilogue: normalize, fp16 hi/lo split, write Yh/Yl [B,T,C] ----
    const float il0 = 1.0f / l0, il1 = 1.0f / l1;
    const int r0g = q0 + wq + l4, r1g = r0g + 8;
#pragma unroll
    for (int nt = 0; nt < 16; ++nt) {
        int col = hh * HD + nt * 8 + 2 * l2;
        size_t o0 = ((size_t)bb * TT + r0g) * CC + col;
        size_t o1 = ((size_t)bb * TT + r1g) * CC + col;
        uint32_t h, l;
        split2h(oacc[nt][0] * il0, oacc[nt][1] * il0, h, l);
        *reinterpret_cast<uint32_t*>(Yh + o0) = h;
        *reinterpret_cast<uint32_t*>(Yl + o0) = l;
        split2h(oacc[nt][2] * il1, oacc[nt][3] * il1, h, l);
        *reinterpret_cast<uint32_t*>(Yh + o1) = h;
        *reinterpret_cast<uint32_t*>(Yl + o1) = l;
    }
}

// ---------------- launch ----------------------------------------------------
extern "C" void kernel_launch(void* const* d_in, const int* in_sizes, int n_in,
                              void* d_out, int out_size)
{
    const float* x    = (const float*)d_in[0];
    const float* Wqkv = (const float*)d_in[1];
    const float* Wout = (const float*)d_in[2];
    float* out = (float*)d_out;

    float* qkv;
    cudaGetSymbolAddress((void**)&qkv, g_qkv);
    __half *xh, *xl, *wqh, *woh, *yh, *yl, *qh, *ql, *kh, *vh;
    cudaGetSymbolAddress((void**)&xh,  g_xh);
    cudaGetSymbolAddress((void**)&xl,  g_xl);
    cudaGetSymbolAddress((void**)&wqh, g_wqh);
    cudaGetSymbolAddress((void**)&woh, g_woh);
    cudaGetSymbolAddress((void**)&yh,  g_yh);
    cudaGetSymbolAddress((void**)&yl,  g_yl);
    cudaGetSymbolAddress((void**)&qh,  g_q_h);
    cudaGetSymbolAddress((void**)&ql,  g_q_l);
    cudaGetSymbolAddress((void**)&kh,  g_k_h);
    cudaGetSymbolAddress((void**)&vh,  g_v_h);

    cudaFuncSetAttribute(gemm_mma_kernel,
                         cudaFuncAttributeMaxDynamicSharedMemorySize,
                         NSTAGE * STG_B);
    cudaFuncSetAttribute(flash_mma_kernel,
                         cudaFuncAttributeMaxDynamicSharedMemorySize,
                         FLASH_SMEM);

    // 0a. split x -> fp16 hi/lo
    {
        size_t n = (size_t)M1 * K1;
        split_kernel<<<(unsigned)(n / 4 / 256), 256>>>(x, xh, xl, n);
    }
    // 0b. transpose weights -> fp16 (hi only)
    transpose_split_kernel<<<dim3(N1 / 32, K1 / 32), dim3(32, 8)>>>(Wqkv, wqh, K1, N1);
    transpose_split_kernel<<<dim3(CC / 32, K1 / 32), dim3(32, 8)>>>(Wout, woh, K1, CC);

    // 1. QKV projection (mma.sync fp16x2, 4-stage pipeline)
    gemm_mma_kernel<<<dim3(N1 / GBN, M1 / GBM), 256, NSTAGE * STG_B>>>(
        xh, xl, wqh, qkv, M1, N1, K1);

    // 2. RoPE + split to fp16 attention operands [B,H,T,hd]
    {
        size_t total = (size_t)BB * TT * CC;
        rope_split_kernel<<<(unsigned)((total + 255) / 256), 256>>>(
            qkv, qh, ql, kh, vh);
    }

    // 3. Flash attention (fp16x2, writes yh/yl directly)
    flash_mma_kernel<<<dim3(TT / AQ2, BB * HH), 256, FLASH_SMEM>>>(
        qh, ql, kh, vh, yh, yl);

    // 4. Output projection (mma.sync fp16x2)
    gemm_mma_kernel<<<dim3(CC / GBN, M1 / GBM), 256, NSTAGE * STG_B>>>(
        yh, yl, woh, out, M1, CC, K1);
}

// round 10
// speedup vs baseline: 1.4804x; 1.0483x over previous
#include <cuda_runtime.h>
#include <cuda_fp16.h>
#include <math.h>
#include <stdint.h>

// Problem dims
#define BB 16
#define TT 512
#define CC 2048
#define HH 16
#define HD 128
#define M1 (BB*TT)        // 8192
#define N1 (3*CC)         // 6144
#define K1 CC             // 2048

// ---------------- scratch (device globals; no allocation allowed) ----------
__device__ __half g_xh[(size_t)M1 * K1];
__device__ __half g_xl[(size_t)M1 * K1];
__device__ __half g_wqh[(size_t)N1 * K1];                // Wqkv^T [6144,2048] fp16
__device__ __half g_woh[(size_t)CC * CC];                // Wout^T [2048,2048] fp16
__device__ __half g_yh[(size_t)M1 * CC];
__device__ __half g_yl[(size_t)M1 * CC];
// attention operands (fp16), [B*H, T, 128]: Q hi/lo exact, K/V hi only
__device__ __half g_q_h[(size_t)BB*HH*TT*HD];
__device__ __half g_q_l[(size_t)BB*HH*TT*HD];
__device__ __half g_k_h[(size_t)BB*HH*TT*HD];
__device__ __half g_v_h[(size_t)BB*HH*TT*HD];

// ======================= PTX helpers (baseline ISA only) ===================
__device__ __forceinline__ uint32_t smem_u32(const void* p) {
    uint32_t a;
    asm("{ .reg .u64 t; cvta.to.shared.u64 t, %1; cvt.u32.u64 %0, t; }"
        : "=r"(a) : "l"(p));
    return a;
}
__device__ __forceinline__ void cpasync16(uint32_t dst, const void* src) {
    asm volatile("cp.async.cg.shared.global [%0], [%1], 16;"
                 :: "r"(dst), "l"(src) : "memory");
}
__device__ __forceinline__ void cpasync_commit() {
    asm volatile("cp.async.commit_group;" ::: "memory");
}
__device__ __forceinline__ void cpasync_wait1() {
    asm volatile("cp.async.wait_group 1;" ::: "memory");
}
__device__ __forceinline__ void cpasync_wait2() {
    asm volatile("cp.async.wait_group 2;" ::: "memory");
}
__device__ __forceinline__ void ldsm_x4(uint32_t& r0, uint32_t& r1,
                                        uint32_t& r2, uint32_t& r3, uint32_t a) {
    asm volatile("ldmatrix.sync.aligned.m8n8.x4.shared.b16 {%0,%1,%2,%3}, [%4];"
                 : "=r"(r0), "=r"(r1), "=r"(r2), "=r"(r3) : "r"(a));
}
__device__ __forceinline__ void ldsm_x4_t(uint32_t& r0, uint32_t& r1,
                                          uint32_t& r2, uint32_t& r3, uint32_t a) {
    asm volatile("ldmatrix.sync.aligned.m8n8.x4.trans.shared.b16 {%0,%1,%2,%3}, [%4];"
                 : "=r"(r0), "=r"(r1), "=r"(r2), "=r"(r3) : "r"(a));
}
// fp16 mma, fp32 accumulate
__device__ __forceinline__ void mma16816f(float* d, const uint32_t* a,
                                          const uint32_t* b) {
    asm volatile(
        "mma.sync.aligned.m16n8k16.row.col.f32.f16.f16.f32 "
        "{%0,%1,%2,%3}, {%4,%5,%6,%7}, {%8,%9}, {%0,%1,%2,%3};"
        : "+f"(d[0]), "+f"(d[1]), "+f"(d[2]), "+f"(d[3])
        : "r"(a[0]), "r"(a[1]), "r"(a[2]), "r"(a[3]), "r"(b[0]), "r"(b[1]));
}
// fp16 hi/lo split of two floats into packed half2 words
__device__ __forceinline__ void split2h(float a, float b, uint32_t& hi, uint32_t& lo) {
    __half ah = __float2half_rn(a), bh = __float2half_rn(b);
    __half al = __float2half_rn(a - __half2float(ah));
    __half bl = __float2half_rn(b - __half2float(bh));
    __half2 h2 = __halves2half2(ah, bh);
    __half2 l2 = __halves2half2(al, bl);
    hi = *reinterpret_cast<uint32_t*>(&h2);
    lo = *reinterpret_cast<uint32_t*>(&l2);
}

// ======================= mma.sync fp16x2 GEMM ==============================
// C[M,N] (f32) = (Ah+Al)[M,K] fp16 @ (Bh [N,K] fp16)^T  -- 2 MMA products.
// mode 0: store C f32.  mode 1: fused RoPE + scale + fp16 split -> q/k/v.
#define GBM 128
#define GBN 128
#define GBK 32
#define TILE_B (128 * 64)            // 8192 B per tile
#define STG_B  (3 * TILE_B)          // Ah, Al, Bh = 24576
#define NSTAGE 4

// conflict-free smem offset: row stride 64B, chunk (16B) XOR'd with (row>>1)&3
__device__ __forceinline__ uint32_t swz(int row, int chunk) {
    return (uint32_t)((row << 6) + ((chunk ^ ((row >> 1) & 3)) << 4));
}

__device__ __forceinline__ void g2s_stage(
    uint32_t sbase,
    const __half* __restrict__ Ah, const __half* __restrict__ Al,
    const __half* __restrict__ Bh,
    int m0, int n0, int k0, int K, int tid)
{
#pragma unroll
    for (int i = 0; i < 2; i++) {
        int s = tid + i * 256;               // 0..511
        int r = s >> 2, c = s & 3;           // row 0..127, 16B chunk 0..3
        uint32_t so = swz(r, c);
        size_t ga = (size_t)(m0 + r) * K + k0 + c * 8;
        size_t gb = (size_t)(n0 + r) * K + k0 + c * 8;
        cpasync16(sbase + 0 * TILE_B + so, Ah + ga);
        cpasync16(sbase + 1 * TILE_B + so, Al + ga);
        cpasync16(sbase + 2 * TILE_B + so, Bh + gb);
    }
}

__global__ __launch_bounds__(256, 2)
void gemm_mma_kernel(const __half* __restrict__ Ah,
                     const __half* __restrict__ Al,
                     const __half* __restrict__ Bh,
                     float* __restrict__ C,
                     __half* __restrict__ Qh, __half* __restrict__ Ql,
                     __half* __restrict__ Kh, __half* __restrict__ Vh,
                     int mode, int M, int N, int K)
{
    extern __shared__ char sm_raw[];
    const uint32_t smbase = smem_u32(sm_raw);
    const int tid = threadIdx.x, wid = tid >> 5, lane = tid & 31;
    const int wm = (wid >> 2) * 64;
    const int wn = (wid & 3) * 32;
    const int m0 = blockIdx.y * GBM;
    const int n0 = blockIdx.x * GBN;
    const int lrow = lane & 15;
    const int lch  = (lane >> 4) & 1;

    float acc[4][4][4];
#pragma unroll
    for (int a = 0; a < 4; a++)
#pragma unroll
        for (int b = 0; b < 4; b++)
#pragma unroll
            for (int c = 0; c < 4; c++) acc[a][b][c] = 0.0f;

    // prologue: fill stages 0..2 (3 outstanding groups)
    g2s_stage(smbase + 0 * STG_B, Ah, Al, Bh, m0, n0, 0 * GBK, K, tid);
    cpasync_commit();
    g2s_stage(smbase + 1 * STG_B, Ah, Al, Bh, m0, n0, 1 * GBK, K, tid);
    cpasync_commit();
    g2s_stage(smbase + 2 * STG_B, Ah, Al, Bh, m0, n0, 2 * GBK, K, tid);
    cpasync_commit();

    const int niter = K / GBK;               // 64
    for (int it = 0; it < niter; ++it) {
        cpasync_wait2();                     // chunk `it` resident
        __syncthreads();
        // refill stage (it+3)&3 == (it-1)&3 — safe: all threads finished
        // iter it-1's LDSMs before reaching the barrier above.
        if (it + 3 < niter)
            g2s_stage(smbase + ((it + 3) & 3) * STG_B, Ah, Al, Bh,
                      m0, n0, (it + 3) * GBK, K, tid);
        cpasync_commit();

        const uint32_t sb = smbase + (it & 3) * STG_B;

#pragma unroll
        for (int kb = 0; kb < 2; ++kb) {
            const int chunk = kb * 2 + lch;
            uint32_t ah[4][4], al[4][4];
#pragma unroll
            for (int mf = 0; mf < 4; ++mf) {
                uint32_t off = swz(wm + mf * 16 + lrow, chunk);
                ldsm_x4(ah[mf][0], ah[mf][1], ah[mf][2], ah[mf][3],
                        sb + 0 * TILE_B + off);
                ldsm_x4(al[mf][0], al[mf][1], al[mf][2], al[mf][3],
                        sb + 1 * TILE_B + off);
            }
            uint32_t bh[4][2];
#pragma unroll
            for (int np = 0; np < 2; ++np) {
                uint32_t off = swz(wn + np * 16 + lrow, chunk);
                uint32_t r0, r1, r2, r3;
                ldsm_x4(r0, r1, r2, r3, sb + 2 * TILE_B + off);
                bh[np*2][0] = r0; bh[np*2][1] = r2;
                bh[np*2+1][0] = r1; bh[np*2+1][1] = r3;
            }
#pragma unroll
            for (int mf = 0; mf < 4; ++mf)
#pragma unroll
                for (int nf = 0; nf < 4; ++nf) {
                    mma16816f(acc[mf][nf], ah[mf], bh[nf]);
                    mma16816f(acc[mf][nf], al[mf], bh[nf]);
                }
        }
        // no trailing sync needed (top-of-loop barrier provides ordering)
    }

    const int l4 = lane >> 2;
    if (mode == 0) {
        const int l2 = (lane & 3) * 2;
#pragma unroll
        for (int mf = 0; mf < 4; ++mf) {
            int r0 = m0 + wm + mf * 16 + l4;
#pragma unroll
            for (int nf = 0; nf < 4; ++nf) {
                int cx = n0 + wn + nf * 8 + l2;
                *(float2*)&C[(size_t)r0 * N + cx] =
                    make_float2(acc[mf][nf][0], acc[mf][nf][1]);
                *(float2*)&C[(size_t)(r0 + 8) * N + cx] =
                    make_float2(acc[mf][nf][2], acc[mf][nf][3]);
            }
        }
    } else {
        // fused epilogue: this 128-col tile is exactly one head of q/k/v.
        const int which = n0 >> 11;            // 0=q, 1=k, 2=v
        const int hh = (n0 & 2047) >> 7;       // head
        const int l2c = (lane & 3) * 2;
        const float qscale = 0.08838834764831845f;
#pragma unroll
        for (int mf = 0; mf < 4; ++mf) {
#pragma unroll
            for (int hf = 0; hf < 2; ++hf) {
                int row = m0 + wm + mf * 16 + l4 + hf * 8;   // global M row
                int t = row & (TT - 1);
                int bbx = row >> 9;
                size_t dbase = (((size_t)(bbx * HH + hh)) * TT + t) * HD;
                float v[4][2];
#pragma unroll
                for (int nf = 0; nf < 4; ++nf) {
                    v[nf][0] = acc[mf][nf][hf * 2 + 0];
                    v[nf][1] = acc[mf][nf][hf * 2 + 1];
                }
                // RoPE: pairs (d, d+8) live in nf=0/1 of the wn==0 warps
                if (which < 2 && wn == 0) {
#pragma unroll
                    for (int c = 0; c < 2; ++c) {
                        int j = l2c + c;                     // 0..7
                        float inv = powf(10000.0f, -(float)j / 8.0f);
                        float sn, cs;
                        sincosf((float)t * inv, &sn, &cs);
                        float x1 = v[0][c], x2 = v[1][c];
                        v[0][c] = x1 * cs - x2 * sn;
                        v[1][c] = x2 * cs + x1 * sn;
                    }
                }
#pragma unroll
                for (int nf = 0; nf < 4; ++nf) {
                    int d0 = wn + nf * 8 + l2c;
                    float a = v[nf][0], b = v[nf][1];
                    if (which == 0) {
                        a *= qscale; b *= qscale;
                        uint32_t hi2, lo2;
                        split2h(a, b, hi2, lo2);
                        *(uint32_t*)(Qh + dbase + d0) = hi2;
                        *(uint32_t*)(Ql + dbase + d0) = lo2;
                    } else {
                        __half2 p = __floats2half2_rn(a, b);
                        if (which == 1) *(__half2*)(Kh + dbase + d0) = p;
                        else            *(__half2*)(Vh + dbase + d0) = p;
                    }
                }
            }
        }
    }
}

// ======================= conversion kernels ================================
// f32 -> fp16 hi/lo
__global__ __launch_bounds__(256)
void split_kernel(const float* __restrict__ in, __half* __restrict__ hi,
                  __half* __restrict__ lo, size_t n)
{
    size_t i = ((size_t)blockIdx.x * blockDim.x + threadIdx.x) * 4;
    if (i >= n) return;
    float4 x = *(const float4*)(in + i);
    uint32_t h0, l0, h1, l1;
    split2h(x.x, x.y, h0, l0);
    split2h(x.z, x.w, h1, l1);
    uint32_t* hp = (uint32_t*)(hi + i);
    uint32_t* lp = (uint32_t*)(lo + i);
    hp[0] = h0; hp[1] = h1;
    lp[0] = l0; lp[1] = l1;
}

// W [K,N] f32 -> Th [N,K] fp16 (hi only)
__global__ __launch_bounds__(256)
void transpose_split_kernel(const float* __restrict__ W,
                            __half* __restrict__ Th, int K, int N)
{
    __shared__ float tile[32][33];
    int n0 = blockIdx.x * 32, k0 = blockIdx.y * 32;
    int tx = threadIdx.x, ty = threadIdx.y;   // 32 x 8
#pragma unroll
    for (int i = 0; i < 32; i += 8)
        tile[ty + i][tx] = W[(size_t)(k0 + ty + i) * N + n0 + tx];
    __syncthreads();
#pragma unroll
    for (int i = 0; i < 32; i += 8) {
        float x = tile[tx][ty + i];
        size_t o = (size_t)(n0 + ty + i) * K + k0 + tx;
        Th[o] = __float2half_rn(x);
    }
}

// ---------------- Flash attention (mma.sync fp16x2, causal) ----------------
// CTA: 128 q-rows (8 warps x 16), kv tile 64, double-buffered KV pipeline.
#define AQ2 128
#define AKV 64
#define Q_TILE_B  (128 * 256)          // 32768 per Q array (hi or lo)
#define KV_TILE_B (64 * 256)           // 16384 per KV array
#define KV_STG_B  (2 * KV_TILE_B)      // Kh, Vh = 32768
#define FLASH_SMEM (2 * Q_TILE_B + 2 * KV_STG_B)   // 131072

__device__ __forceinline__ uint32_t aswz(int row, int chunk) {
    return (uint32_t)((row << 8) + ((chunk ^ (row & 7)) << 4));
}

__device__ __forceinline__ void kv_stage_load(
    uint32_t skv,
    const __half* __restrict__ Kh, const __half* __restrict__ Vh,
    size_t kg, int tid)
{
#pragma unroll
    for (int i = 0; i < 4; i++) {
        int s = tid + i * 256;            // 0..1023
        int r = s >> 4, c = s & 15;       // 64 rows x 16 chunks
        uint32_t so = aswz(r, c);
        size_t go = kg + (size_t)r * HD + c * 8;
        cpasync16(skv + 0 * KV_TILE_B + so, Kh + go);
        cpasync16(skv + 1 * KV_TILE_B + so, Vh + go);
    }
}

__global__ __launch_bounds__(256)
void flash_mma_kernel(const __half* __restrict__ Qh, const __half* __restrict__ Ql,
                      const __half* __restrict__ Kh, const __half* __restrict__ Vh,
                      __half* __restrict__ Yh, __half* __restrict__ Yl)
{
    extern __shared__ char smraw[];
    const uint32_t sbse = smem_u32(smraw);
    const uint32_t sQh = sbse, sQl = sbse + Q_TILE_B;
    const uint32_t sKV0 = sbse + 2 * Q_TILE_B;

    const int tid = threadIdx.x, lane = tid & 31, wid = tid >> 5;
    const int qt = blockIdx.x, bhid = blockIdx.y;
    const int bb = bhid >> 4, hh = bhid & 15;
    const int q0 = qt * AQ2;
    const int l4 = lane >> 2, l2 = lane & 3;
    const int lrow = lane & 15, lch = lane >> 4;
    const int wq = wid * 16;                 // warp q-row base: 0..112

    const int jtmax = 2 * qt + 1;            // kv tiles 0..jtmax

    // G0: Q tile + KV stage 0
    const size_t qg = ((size_t)bhid * TT + q0) * HD;
#pragma unroll
    for (int i = 0; i < 8; i++) {
        int s = tid + i * 256;            // 0..2047
        int r = s >> 4, c = s & 15;       // 128 rows x 16 chunks
        uint32_t so = aswz(r, c);
        size_t go = qg + (size_t)r * HD + c * 8;
        cpasync16(sQh + so, Qh + go);
        cpasync16(sQl + so, Ql + go);
    }
    const size_t kvbase = (size_t)bhid * TT * HD;
    kv_stage_load(sKV0, Kh, Vh, kvbase, tid);
    cpasync_commit();
    kv_stage_load(sKV0 + KV_STG_B, Kh, Vh, kvbase + (size_t)AKV * HD, tid);
    cpasync_commit();

    float m0 = -1e30f, m1 = -1e30f, l0 = 0.0f, l1 = 0.0f;
    float oacc[16][4];
#pragma unroll
    for (int i = 0; i < 16; i++)
#pragma unroll
        for (int j = 0; j < 4; j++) oacc[i][j] = 0.0f;

    for (int jt = 0; jt <= jtmax; ++jt) {
        cpasync_wait1();                 // stage jt resident (one group pending)
        __syncthreads();

        const uint32_t skv = sKV0 + (jt & 1) * KV_STG_B;
        const uint32_t sk_h = skv, sv_h = skv + KV_TILE_B;

        // ---- S = Q K^T (pre-scaled Q; fp32 acc; fp16x2) ----
        float sacc[8][4];
#pragma unroll
        for (int i = 0; i < 8; i++)
#pragma unroll
            for (int j = 0; j < 4; j++) sacc[i][j] = 0.0f;

#pragma unroll
        for (int kb = 0; kb < 8; ++kb) {
            const int chunk = kb * 2 + lch;
            const uint32_t qa = aswz(wq + lrow, chunk);
            uint32_t ah[4], al[4];
            ldsm_x4(ah[0], ah[1], ah[2], ah[3], sQh + qa);
            ldsm_x4(al[0], al[1], al[2], al[3], sQl + qa);
#pragma unroll
            for (int np = 0; np < 4; ++np) {
                const uint32_t ka = aswz(np * 16 + lrow, chunk);
                uint32_t r0, r1, r2, r3;
                ldsm_x4(r0, r1, r2, r3, sk_h + ka);
                uint32_t b0[2] = {r0, r2}, b1[2] = {r1, r3};
                mma16816f(sacc[np*2],   ah, b0);
                mma16816f(sacc[np*2],   al, b0);
                mma16816f(sacc[np*2+1], ah, b1);
                mma16816f(sacc[np*2+1], al, b1);
            }
        }

        // ---- causal mask (diagonal-region tiles) ----
        if (jt >= 2 * qt) {
            const int r0g = q0 + wq + l4, r1g = r0g + 8;
#pragma unroll
            for (int nf = 0; nf < 8; ++nf) {
                int c0 = jt * AKV + nf * 8 + 2 * l2;
                if (c0     > r0g) sacc[nf][0] = -1e30f;
                if (c0 + 1 > r0g) sacc[nf][1] = -1e30f;
                if (c0     > r1g) sacc[nf][2] = -1e30f;
                if (c0 + 1 > r1g) sacc[nf][3] = -1e30f;
            }
        }

        // ---- online softmax ----
        float rx0 = -1e30f, rx1 = -1e30f;
#pragma unroll
        for (int nf = 0; nf < 8; ++nf) {
            rx0 = fmaxf(rx0, fmaxf(sacc[nf][0], sacc[nf][1]));
            rx1 = fmaxf(rx1, fmaxf(sacc[nf][2], sacc[nf][3]));
        }
#pragma unroll
        for (int off = 2; off >= 1; off >>= 1) {
            rx0 = fmaxf(rx0, __shfl_xor_sync(0xffffffffu, rx0, off));
            rx1 = fmaxf(rx1, __shfl_xor_sync(0xffffffffu, rx1, off));
        }
        float nm0 = fmaxf(m0, rx0), nm1 = fmaxf(m1, rx1);
        float a0 = __expf(m0 - nm0), a1 = __expf(m1 - nm1);
        m0 = nm0; m1 = nm1;
        float s0 = 0.0f, s1 = 0.0f;
#pragma unroll
        for (int nf = 0; nf < 8; ++nf) {
            sacc[nf][0] = __expf(sacc[nf][0] - nm0); s0 += sacc[nf][0];
            sacc[nf][1] = __expf(sacc[nf][1] - nm0); s0 += sacc[nf][1];
            sacc[nf][2] = __expf(sacc[nf][2] - nm1); s1 += sacc[nf][2];
            sacc[nf][3] = __expf(sacc[nf][3] - nm1); s1 += sacc[nf][3];
        }
#pragma unroll
        for (int off = 2; off >= 1; off >>= 1) {
            s0 += __shfl_xor_sync(0xffffffffu, s0, off);
            s1 += __shfl_xor_sync(0xffffffffu, s1, off);
        }
        l0 = l0 * a0 + s0;
        l1 = l1 * a1 + s1;
#pragma unroll
        for (int nt = 0; nt < 16; ++nt) {
            oacc[nt][0] *= a0; oacc[nt][1] *= a0;
            oacc[nt][2] *= a1; oacc[nt][3] *= a1;
        }

        // ---- O += P V (P exact via fp16 hi/lo; V fp16 hi) ----
#pragma unroll
        for (int kt = 0; kt < 4; ++kt) {
            uint32_t ph[4], pl[4];
            split2h(sacc[2*kt][0],   sacc[2*kt][1],   ph[0], pl[0]);
            split2h(sacc[2*kt][2],   sacc[2*kt][3],   ph[1], pl[1]);
            split2h(sacc[2*kt+1][0], sacc[2*kt+1][1], ph[2], pl[2]);
            split2h(sacc[2*kt+1][2], sacc[2*kt+1][3], ph[3], pl[3]);
#pragma unroll
            for (int nd = 0; nd < 8; ++nd) {
                const uint32_t va = aswz(kt * 16 + lrow, nd * 2 + lch);
                uint32_t h0, h1, h2, h3;
                ldsm_x4_t(h0, h1, h2, h3, sv_h + va);
                uint32_t vb0[2] = {h0, h1}, vb1[2] = {h2, h3};
                mma16816f(oacc[nd*2],   ph, vb0);
                mma16816f(oacc[nd*2],   pl, vb0);
                mma16816f(oacc[nd*2+1], ph, vb1);
                mma16816f(oacc[nd*2+1], pl, vb1);
            }
        }

        // refill the stage just consumed (stage jt&1) for tile jt+2
        __syncthreads();
        if (jt + 2 <= jtmax)
            kv_stage_load(sKV0 + (jt & 1) * KV_STG_B, Kh, Vh,
                          kvbase + (size_t)(jt + 2) * AKV * HD, tid);
        cpasync_commit();                // one group per iter (may be empty)
    }

    // ---- epilogue: normalize, fp16 hi/lo split, write Yh/Yl [B,T,C] ----
    const float il0 = 1.0f / l0, il1 = 1.0f / l1;
    const int r0g = q0 + wq + l4, r1g = r0g + 8;
#pragma unroll
    for (int nt = 0; nt < 16; ++nt) {
        int col = hh * HD + nt * 8 + 2 * l2;
        size_t o0 = ((size_t)bb * TT + r0g) * CC + col;
        size_t o1 = ((size_t)bb * TT + r1g) * CC + col;
        uint32_t h, l;
        split2h(oacc[nt][0] * il0, oacc[nt][1] * il0, h, l);
        *reinterpret_cast<uint32_t*>(Yh + o0) = h;
        *reinterpret_cast<uint32_t*>(Yl + o0) = l;
        split2h(oacc[nt][2] * il1, oacc[nt][3] * il1, h, l);
        *reinterpret_cast<uint32_t*>(Yh + o1) = h;
        *reinterpret_cast<uint32_t*>(Yl + o1) = l;
    }
}

// ---------------- launch ----------------------------------------------------
extern "C" void kernel_launch(void* const* d_in, const int* in_sizes, int n_in,
                              void* d_out, int out_size)
{
    const float* x    = (const float*)d_in[0];
    const float* Wqkv = (const float*)d_in[1];
    const float* Wout = (const float*)d_in[2];
    float* out = (float*)d_out;

    __half *xh, *xl, *wqh, *woh, *yh, *yl, *qh, *ql, *kh, *vh;
    cudaGetSymbolAddress((void**)&xh,  g_xh);
    cudaGetSymbolAddress((void**)&xl,  g_xl);
    cudaGetSymbolAddress((void**)&wqh, g_wqh);
    cudaGetSymbolAddress((void**)&woh, g_woh);
    cudaGetSymbolAddress((void**)&yh,  g_yh);
    cudaGetSymbolAddress((void**)&yl,  g_yl);
    cudaGetSymbolAddress((void**)&qh,  g_q_h);
    cudaGetSymbolAddress((void**)&ql,  g_q_l);
    cudaGetSymbolAddress((void**)&kh,  g_k_h);
    cudaGetSymbolAddress((void**)&vh,  g_v_h);

    cudaFuncSetAttribute(gemm_mma_kernel,
                         cudaFuncAttributeMaxDynamicSharedMemorySize,
                         NSTAGE * STG_B);
    cudaFuncSetAttribute(flash_mma_kernel,
                         cudaFuncAttributeMaxDynamicSharedMemorySize,
                         FLASH_SMEM);

    // 0a. split x -> fp16 hi/lo
    {
        size_t n = (size_t)M1 * K1;
        split_kernel<<<(unsigned)(n / 4 / 256), 256>>>(x, xh, xl, n);
    }
    // 0b. transpose weights -> fp16 (hi only)
    transpose_split_kernel<<<dim3(N1 / 32, K1 / 32), dim3(32, 8)>>>(Wqkv, wqh, K1, N1);
    transpose_split_kernel<<<dim3(CC / 32, K1 / 32), dim3(32, 8)>>>(Wout, woh, K1, CC);

    // 1. QKV projection + fused RoPE/scale/fp16-split epilogue
    gemm_mma_kernel<<<dim3(N1 / GBN, M1 / GBM), 256, NSTAGE * STG_B>>>(
        xh, xl, wqh, nullptr, qh, ql, kh, vh, 1, M1, N1, K1);

    // 2. Flash attention (fp16x2, writes yh/yl directly)
    flash_mma_kernel<<<dim3(TT / AQ2, BB * HH), 256, FLASH_SMEM>>>(
        qh, ql, kh, vh, yh, yl);

    // 3. Output projection (plain f32 epilogue)
    gemm_mma_kernel<<<dim3(CC / GBN, M1 / GBM), 256, NSTAGE * STG_B>>>(
        yh, yl, woh, out, nullptr, nullptr, nullptr, nullptr, 0, M1, CC, K1);
}

// round 11
// speedup vs baseline: 2.5495x; 1.7221x over previous
#include <cuda_runtime.h>
#include <cuda_fp16.h>
#include <math.h>
#include <stdint.h>

// Problem dims
#define BB 16
#define TT 512
#define CC 2048
#define HH 16
#define HD 128
#define M1 (BB*TT)        // 8192
#define N1 (3*CC)         // 6144
#define K1 CC             // 2048

// ---------------- scratch (device globals; no allocation allowed) ----------
__device__ __half g_xh[(size_t)M1 * K1];
__device__ __half g_wqh[(size_t)N1 * K1];                // Wqkv^T [6144,2048] fp16
__device__ __half g_woh[(size_t)CC * CC];                // Wout^T [2048,2048] fp16
__device__ __half g_yh[(size_t)M1 * CC];
// attention operands (fp16), [B*H, T, 128]: Q hi/lo exact, K/V hi only
__device__ __half g_q_h[(size_t)BB*HH*TT*HD];
__device__ __half g_q_l[(size_t)BB*HH*TT*HD];
__device__ __half g_k_h[(size_t)BB*HH*TT*HD];
__device__ __half g_v_h[(size_t)BB*HH*TT*HD];

// ======================= PTX helpers (baseline ISA only) ===================
__device__ __forceinline__ uint32_t smem_u32(const void* p) {
    uint32_t a;
    asm("{ .reg .u64 t; cvta.to.shared.u64 t, %1; cvt.u32.u64 %0, t; }"
        : "=r"(a) : "l"(p));
    return a;
}
__device__ __forceinline__ void cpasync16(uint32_t dst, const void* src) {
    asm volatile("cp.async.cg.shared.global [%0], [%1], 16;"
                 :: "r"(dst), "l"(src) : "memory");
}
__device__ __forceinline__ void cpasync_commit() {
    asm volatile("cp.async.commit_group;" ::: "memory");
}
__device__ __forceinline__ void cpasync_wait1() {
    asm volatile("cp.async.wait_group 1;" ::: "memory");
}
__device__ __forceinline__ void cpasync_wait2() {
    asm volatile("cp.async.wait_group 2;" ::: "memory");
}
__device__ __forceinline__ void ldsm_x4(uint32_t& r0, uint32_t& r1,
                                        uint32_t& r2, uint32_t& r3, uint32_t a) {
    asm volatile("ldmatrix.sync.aligned.m8n8.x4.shared.b16 {%0,%1,%2,%3}, [%4];"
                 : "=r"(r0), "=r"(r1), "=r"(r2), "=r"(r3) : "r"(a));
}
__device__ __forceinline__ void ldsm_x4_t(uint32_t& r0, uint32_t& r1,
                                          uint32_t& r2, uint32_t& r3, uint32_t a) {
    asm volatile("ldmatrix.sync.aligned.m8n8.x4.trans.shared.b16 {%0,%1,%2,%3}, [%4];"
                 : "=r"(r0), "=r"(r1), "=r"(r2), "=r"(r3) : "r"(a));
}
// fp16 mma, fp32 accumulate
__device__ __forceinline__ void mma16816f(float* d, const uint32_t* a,
                                          const uint32_t* b) {
    asm volatile(
        "mma.sync.aligned.m16n8k16.row.col.f32.f16.f16.f32 "
        "{%0,%1,%2,%3}, {%4,%5,%6,%7}, {%8,%9}, {%0,%1,%2,%3};"
        : "+f"(d[0]), "+f"(d[1]), "+f"(d[2]), "+f"(d[3])
        : "r"(a[0]), "r"(a[1]), "r"(a[2]), "r"(a[3]), "r"(b[0]), "r"(b[1]));
}
// fp16 hi/lo split of two floats into packed half2 words
__device__ __forceinline__ void split2h(float a, float b, uint32_t& hi, uint32_t& lo) {
    __half ah = __float2half_rn(a), bh = __float2half_rn(b);
    __half al = __float2half_rn(a - __half2float(ah));
    __half bl = __float2half_rn(b - __half2float(bh));
    __half2 h2 = __halves2half2(ah, bh);
    __half2 l2 = __halves2half2(al, bl);
    hi = *reinterpret_cast<uint32_t*>(&h2);
    lo = *reinterpret_cast<uint32_t*>(&l2);
}

// ======================= mma.sync fp16 GEMM ================================
// C[M,N] (f32) = Ah[M,K] fp16 @ (Bh [N,K] fp16)^T  -- single product.
// mode 0: store C f32.  mode 1: fused RoPE + scale + fp16 split -> q/k/v.
#define GBM 128
#define GBN 128
#define GBK 32
#define TILE_B (128 * 64)            // 8192 B per tile
#define STG_B  (2 * TILE_B)          // Ah, Bh = 16384
#define NSTAGE 4

// conflict-free smem offset: row stride 64B, chunk (16B) XOR'd with (row>>1)&3
__device__ __forceinline__ uint32_t swz(int row, int chunk) {
    return (uint32_t)((row << 6) + ((chunk ^ ((row >> 1) & 3)) << 4));
}

__device__ __forceinline__ void g2s_stage(
    uint32_t sbase,
    const __half* __restrict__ Ah, const __half* __restrict__ Bh,
    int m0, int n0, int k0, int K, int tid)
{
#pragma unroll
    for (int i = 0; i < 2; i++) {
        int s = tid + i * 256;               // 0..511
        int r = s >> 2, c = s & 3;           // row 0..127, 16B chunk 0..3
        uint32_t so = swz(r, c);
        size_t ga = (size_t)(m0 + r) * K + k0 + c * 8;
        size_t gb = (size_t)(n0 + r) * K + k0 + c * 8;
        cpasync16(sbase + 0 * TILE_B + so, Ah + ga);
        cpasync16(sbase + 1 * TILE_B + so, Bh + gb);
    }
}

__global__ __launch_bounds__(256, 2)
void gemm_mma_kernel(const __half* __restrict__ Ah,
                     const __half* __restrict__ Bh,
                     float* __restrict__ C,
                     __half* __restrict__ Qh, __half* __restrict__ Ql,
                     __half* __restrict__ Kh, __half* __restrict__ Vh,
                     int mode, int M, int N, int K)
{
    extern __shared__ char sm_raw[];
    const uint32_t smbase = smem_u32(sm_raw);
    const int tid = threadIdx.x, wid = tid >> 5, lane = tid & 31;
    const int wm = (wid >> 2) * 64;
    const int wn = (wid & 3) * 32;
    const int m0 = blockIdx.y * GBM;
    const int n0 = blockIdx.x * GBN;
    const int lrow = lane & 15;
    const int lch  = (lane >> 4) & 1;

    float acc[4][4][4];
#pragma unroll
    for (int a = 0; a < 4; a++)
#pragma unroll
        for (int b = 0; b < 4; b++)
#pragma unroll
            for (int c = 0; c < 4; c++) acc[a][b][c] = 0.0f;

    // prologue: fill stages 0..2 (3 outstanding groups)
    g2s_stage(smbase + 0 * STG_B, Ah, Bh, m0, n0, 0 * GBK, K, tid);
    cpasync_commit();
    g2s_stage(smbase + 1 * STG_B, Ah, Bh, m0, n0, 1 * GBK, K, tid);
    cpasync_commit();
    g2s_stage(smbase + 2 * STG_B, Ah, Bh, m0, n0, 2 * GBK, K, tid);
    cpasync_commit();

    const int niter = K / GBK;               // 64
    for (int it = 0; it < niter; ++it) {
        cpasync_wait2();                     // chunk `it` resident
        __syncthreads();
        // refill stage (it+3)&3 == (it-1)&3 — safe: all threads finished
        // iter it-1's LDSMs before reaching the barrier above.
        if (it + 3 < niter)
            g2s_stage(smbase + ((it + 3) & 3) * STG_B, Ah, Bh,
                      m0, n0, (it + 3) * GBK, K, tid);
        cpasync_commit();

        const uint32_t sb = smbase + (it & 3) * STG_B;

#pragma unroll
        for (int kb = 0; kb < 2; ++kb) {
            const int chunk = kb * 2 + lch;
            uint32_t ah[4][4];
#pragma unroll
            for (int mf = 0; mf < 4; ++mf) {
                uint32_t off = swz(wm + mf * 16 + lrow, chunk);
                ldsm_x4(ah[mf][0], ah[mf][1], ah[mf][2], ah[mf][3],
                        sb + 0 * TILE_B + off);
            }
            uint32_t bh[4][2];
#pragma unroll
            for (int np = 0; np < 2; ++np) {
                uint32_t off = swz(wn + np * 16 + lrow, chunk);
                uint32_t r0, r1, r2, r3;
                ldsm_x4(r0, r1, r2, r3, sb + 1 * TILE_B + off);
                bh[np*2][0] = r0; bh[np*2][1] = r2;
                bh[np*2+1][0] = r1; bh[np*2+1][1] = r3;
            }
#pragma unroll
            for (int mf = 0; mf < 4; ++mf)
#pragma unroll
                for (int nf = 0; nf < 4; ++nf)
                    mma16816f(acc[mf][nf], ah[mf], bh[nf]);
        }
    }

    const int l4 = lane >> 2;
    if (mode == 0) {
        const int l2 = (lane & 3) * 2;
#pragma unroll
        for (int mf = 0; mf < 4; ++mf) {
            int r0 = m0 + wm + mf * 16 + l4;
#pragma unroll
            for (int nf = 0; nf < 4; ++nf) {
                int cx = n0 + wn + nf * 8 + l2;
                *(float2*)&C[(size_t)r0 * N + cx] =
                    make_float2(acc[mf][nf][0], acc[mf][nf][1]);
                *(float2*)&C[(size_t)(r0 + 8) * N + cx] =
                    make_float2(acc[mf][nf][2], acc[mf][nf][3]);
            }
        }
    } else {
        // fused epilogue: this 128-col tile is exactly one head of q/k/v.
        const int which = n0 >> 11;            // 0=q, 1=k, 2=v
        const int hh = (n0 & 2047) >> 7;       // head
        const int l2c = (lane & 3) * 2;
        const float qscale = 0.08838834764831845f;
#pragma unroll
        for (int mf = 0; mf < 4; ++mf) {
#pragma unroll
            for (int hf = 0; hf < 2; ++hf) {
                int row = m0 + wm + mf * 16 + l4 + hf * 8;   // global M row
                int t = row & (TT - 1);
                int bbx = row >> 9;
                size_t dbase = (((size_t)(bbx * HH + hh)) * TT + t) * HD;
                float v[4][2];
#pragma unroll
                for (int nf = 0; nf < 4; ++nf) {
                    v[nf][0] = acc[mf][nf][hf * 2 + 0];
                    v[nf][1] = acc[mf][nf][hf * 2 + 1];
                }
                // RoPE: pairs (d, d+8) live in nf=0/1 of the wn==0 warps
                if (which < 2 && wn == 0) {
#pragma unroll
                    for (int c = 0; c < 2; ++c) {
                        int j = l2c + c;                     // 0..7
                        float inv = powf(10000.0f, -(float)j / 8.0f);
                        float sn, cs;
                        sincosf((float)t * inv, &sn, &cs);
                        float x1 = v[0][c], x2 = v[1][c];
                        v[0][c] = x1 * cs - x2 * sn;
                        v[1][c] = x2 * cs + x1 * sn;
                    }
                }
#pragma unroll
                for (int nf = 0; nf < 4; ++nf) {
                    int d0 = wn + nf * 8 + l2c;
                    float a = v[nf][0], b = v[nf][1];
                    if (which == 0) {
                        a *= qscale; b *= qscale;
                        uint32_t hi2, lo2;
                        split2h(a, b, hi2, lo2);
                        *(uint32_t*)(Qh + dbase + d0) = hi2;
                        *(uint32_t*)(Ql + dbase + d0) = lo2;
                    } else {
                        __half2 p = __floats2half2_rn(a, b);
                        if (which == 1) *(__half2*)(Kh + dbase + d0) = p;
                        else            *(__half2*)(Vh + dbase + d0) = p;
                    }
                }
            }
        }
    }
}

// ======================= conversion kernels ================================
// f32 -> fp16 (hi only)
__global__ __launch_bounds__(256)
void split_kernel(const float* __restrict__ in, __half* __restrict__ hi, size_t n)
{
    size_t i = ((size_t)blockIdx.x * blockDim.x + threadIdx.x) * 4;
    if (i >= n) return;
    float4 x = *(const float4*)(in + i);
    __half2 h0 = __floats2half2_rn(x.x, x.y);
    __half2 h1 = __floats2half2_rn(x.z, x.w);
    uint32_t* hp = (uint32_t*)(hi + i);
    hp[0] = *reinterpret_cast<uint32_t*>(&h0);
    hp[1] = *reinterpret_cast<uint32_t*>(&h1);
}

// W [K,N] f32 -> Th [N,K] fp16 (hi only)
__global__ __launch_bounds__(256)
void transpose_split_kernel(const float* __restrict__ W,
                            __half* __restrict__ Th, int K, int N)
{
    __shared__ float tile[32][33];
    int n0 = blockIdx.x * 32, k0 = blockIdx.y * 32;
    int tx = threadIdx.x, ty = threadIdx.y;   // 32 x 8
#pragma unroll
    for (int i = 0; i < 32; i += 8)
        tile[ty + i][tx] = W[(size_t)(k0 + ty + i) * N + n0 + tx];
    __syncthreads();
#pragma unroll
    for (int i = 0; i < 32; i += 8) {
        float x = tile[tx][ty + i];
        size_t o = (size_t)(n0 + ty + i) * K + k0 + tx;
        Th[o] = __float2half_rn(x);
    }
}

// ---------------- Flash attention (mma.sync fp16, causal) ------------------
// CTA: 128 q-rows (8 warps x 16), kv tile 64, double-buffered KV pipeline.
#define AQ2 128
#define AKV 64
#define Q_TILE_B  (128 * 256)          // 32768 per Q array (hi or lo)
#define KV_TILE_B (64 * 256)           // 16384 per KV array
#define KV_STG_B  (2 * KV_TILE_B)      // Kh, Vh = 32768
#define FLASH_SMEM (2 * Q_TILE_B + 2 * KV_STG_B)   // 131072

__device__ __forceinline__ uint32_t aswz(int row, int chunk) {
    return (uint32_t)((row << 8) + ((chunk ^ (row & 7)) << 4));
}

__device__ __forceinline__ void kv_stage_load(
    uint32_t skv,
    const __half* __restrict__ Kh, const __half* __restrict__ Vh,
    size_t kg, int tid)
{
#pragma unroll
    for (int i = 0; i < 4; i++) {
        int s = tid + i * 256;            // 0..1023
        int r = s >> 4, c = s & 15;       // 64 rows x 16 chunks
        uint32_t so = aswz(r, c);
        size_t go = kg + (size_t)r * HD + c * 8;
        cpasync16(skv + 0 * KV_TILE_B + so, Kh + go);
        cpasync16(skv + 1 * KV_TILE_B + so, Vh + go);
    }
}

__global__ __launch_bounds__(256)
void flash_mma_kernel(const __half* __restrict__ Qh, const __half* __restrict__ Ql,
                      const __half* __restrict__ Kh, const __half* __restrict__ Vh,
                      __half* __restrict__ Yh)
{
    extern __shared__ char smraw[];
    const uint32_t sbse = smem_u32(smraw);
    const uint32_t sQh = sbse, sQl = sbse + Q_TILE_B;
    const uint32_t sKV0 = sbse + 2 * Q_TILE_B;

    const int tid = threadIdx.x, lane = tid & 31, wid = tid >> 5;
    const int qt = blockIdx.x, bhid = blockIdx.y;
    const int bb = bhid >> 4, hh = bhid & 15;
    const int q0 = qt * AQ2;
    const int l4 = lane >> 2, l2 = lane & 3;
    const int lrow = lane & 15, lch = lane >> 4;
    const int wq = wid * 16;                 // warp q-row base: 0..112

    const int jtmax = 2 * qt + 1;            // kv tiles 0..jtmax

    // G0: Q tile + KV stage 0
    const size_t qg = ((size_t)bhid * TT + q0) * HD;
#pragma unroll
    for (int i = 0; i < 8; i++) {
        int s = tid + i * 256;            // 0..2047
        int r = s >> 4, c = s & 15;       // 128 rows x 16 chunks
        uint32_t so = aswz(r, c);
        size_t go = qg + (size_t)r * HD + c * 8;
        cpasync16(sQh + so, Qh + go);
        cpasync16(sQl + so, Ql + go);
    }
    const size_t kvbase = (size_t)bhid * TT * HD;
    kv_stage_load(sKV0, Kh, Vh, kvbase, tid);
    cpasync_commit();
    kv_stage_load(sKV0 + KV_STG_B, Kh, Vh, kvbase + (size_t)AKV * HD, tid);
    cpasync_commit();

    float m0 = -1e30f, m1 = -1e30f, l0 = 0.0f, l1 = 0.0f;
    float oacc[16][4];
#pragma unroll
    for (int i = 0; i < 16; i++)
#pragma unroll
        for (int j = 0; j < 4; j++) oacc[i][j] = 0.0f;

    for (int jt = 0; jt <= jtmax; ++jt) {
        cpasync_wait1();                 // stage jt resident (one group pending)
        __syncthreads();

        const uint32_t skv = sKV0 + (jt & 1) * KV_STG_B;
        const uint32_t sk_h = skv, sv_h = skv + KV_TILE_B;

        // ---- S = Q K^T (pre-scaled Q; fp32 acc; Q exact via hi/lo) ----
        float sacc[8][4];
#pragma unroll
        for (int i = 0; i < 8; i++)
#pragma unroll
            for (int j = 0; j < 4; j++) sacc[i][j] = 0.0f;

#pragma unroll
        for (int kb = 0; kb < 8; ++kb) {
            const int chunk = kb * 2 + lch;
            const uint32_t qa = aswz(wq + lrow, chunk);
            uint32_t ah[4], al[4];
            ldsm_x4(ah[0], ah[1], ah[2], ah[3], sQh + qa);
            ldsm_x4(al[0], al[1], al[2], al[3], sQl + qa);
#pragma unroll
            for (int np = 0; np < 4; ++np) {
                const uint32_t ka = aswz(np * 16 + lrow, chunk);
                uint32_t r0, r1, r2, r3;
                ldsm_x4(r0, r1, r2, r3, sk_h + ka);
                uint32_t b0[2] = {r0, r2}, b1[2] = {r1, r3};
                mma16816f(sacc[np*2],   ah, b0);
                mma16816f(sacc[np*2],   al, b0);
                mma16816f(sacc[np*2+1], ah, b1);
                mma16816f(sacc[np*2+1], al, b1);
            }
        }

        // ---- causal mask (diagonal-region tiles) ----
        if (jt >= 2 * qt) {
            const int r0g = q0 + wq + l4, r1g = r0g + 8;
#pragma unroll
            for (int nf = 0; nf < 8; ++nf) {
                int c0 = jt * AKV + nf * 8 + 2 * l2;
                if (c0     > r0g) sacc[nf][0] = -1e30f;
                if (c0 + 1 > r0g) sacc[nf][1] = -1e30f;
                if (c0     > r1g) sacc[nf][2] = -1e30f;
                if (c0 + 1 > r1g) sacc[nf][3] = -1e30f;
            }
        }

        // ---- online softmax ----
        float rx0 = -1e30f, rx1 = -1e30f;
#pragma unroll
        for (int nf = 0; nf < 8; ++nf) {
            rx0 = fmaxf(rx0, fmaxf(sacc[nf][0], sacc[nf][1]));
            rx1 = fmaxf(rx1, fmaxf(sacc[nf][2], sacc[nf][3]));
        }
#pragma unroll
        for (int off = 2; off >= 1; off >>= 1) {
            rx0 = fmaxf(rx0, __shfl_xor_sync(0xffffffffu, rx0, off));
            rx1 = fmaxf(rx1, __shfl_xor_sync(0xffffffffu, rx1, off));
        }
        float nm0 = fmaxf(m0, rx0), nm1 = fmaxf(m1, rx1);
        float a0 = __expf(m0 - nm0), a1 = __expf(m1 - nm1);
        m0 = nm0; m1 = nm1;
        float s0 = 0.0f, s1 = 0.0f;
#pragma unroll
        for (int nf = 0; nf < 8; ++nf) {
            sacc[nf][0] = __expf(sacc[nf][0] - nm0); s0 += sacc[nf][0];
            sacc[nf][1] = __expf(sacc[nf][1] - nm0); s0 += sacc[nf][1];
            sacc[nf][2] = __expf(sacc[nf][2] - nm1); s1 += sacc[nf][2];
            sacc[nf][3] = __expf(sacc[nf][3] - nm1); s1 += sacc[nf][3];
        }
#pragma unroll
        for (int off = 2; off >= 1; off >>= 1) {
            s0 += __shfl_xor_sync(0xffffffffu, s0, off);
            s1 += __shfl_xor_sync(0xffffffffu, s1, off);
        }
        l0 = l0 * a0 + s0;
        l1 = l1 * a1 + s1;
#pragma unroll
        for (int nt = 0; nt < 16; ++nt) {
            oacc[nt][0] *= a0; oacc[nt][1] *= a0;
            oacc[nt][2] *= a1; oacc[nt][3] *= a1;
        }

        // ---- O += P V (P exact via fp16 hi/lo; V fp16 hi) ----
#pragma unroll
        for (int kt = 0; kt < 4; ++kt) {
            uint32_t ph[4], pl[4];
            split2h(sacc[2*kt][0],   sacc[2*kt][1],   ph[0], pl[0]);
            split2h(sacc[2*kt][2],   sacc[2*kt][3],   ph[1], pl[1]);
            split2h(sacc[2*kt+1][0], sacc[2*kt+1][1], ph[2], pl[2]);
            split2h(sacc[2*kt+1][2], sacc[2*kt+1][3], ph[3], pl[3]);
#pragma unroll
            for (int nd = 0; nd < 8; ++nd) {
                const uint32_t va = aswz(kt * 16 + lrow, nd * 2 + lch);
                uint32_t h0, h1, h2, h3;
                ldsm_x4_t(h0, h1, h2, h3, sv_h + va);
                uint32_t vb0[2] = {h0, h1}, vb1[2] = {h2, h3};
                mma16816f(oacc[nd*2],   ph, vb0);
                mma16816f(oacc[nd*2],   pl, vb0);
                mma16816f(oacc[nd*2+1], ph, vb1);
                mma16816f(oacc[nd*2+1], pl, vb1);
            }
        }

        // refill the stage just consumed (stage jt&1) for tile jt+2
        __syncthreads();
        if (jt + 2 <= jtmax)
            kv_stage_load(sKV0 + (jt & 1) * KV_STG_B, Kh, Vh,
                          kvbase + (size_t)(jt + 2) * AKV * HD, tid);
        cpasync_commit();                // one group per iter (may be empty)
    }

    // ---- epilogue: normalize, fp16 round, write Yh [B,T,C] ----
    const float il0 = 1.0f / l0, il1 = 1.0f / l1;
    const int r0g = q0 + wq + l4, r1g = r0g + 8;
#pragma unroll
    for (int nt = 0; nt < 16; ++nt) {
        int col = hh * HD + nt * 8 + 2 * l2;
        size_t o0 = ((size_t)bb * TT + r0g) * CC + col;
        size_t o1 = ((size_t)bb * TT + r1g) * CC + col;
        __half2 p0 = __floats2half2_rn(oacc[nt][0] * il0, oacc[nt][1] * il0);
        __half2 p1 = __floats2half2_rn(oacc[nt][2] * il1, oacc[nt][3] * il1);
        *(__half2*)(Yh + o0) = p0;
        *(__half2*)(Yh + o1) = p1;
    }
}

// ---------------- launch ----------------------------------------------------
extern "C" void kernel_launch(void* const* d_in, const int* in_sizes, int n_in,
                              void* d_out, int out_size)
{
    const float* x    = (const float*)d_in[0];
    const float* Wqkv = (const float*)d_in[1];
    const float* Wout = (const float*)d_in[2];
    float* out = (float*)d_out;

    __half *xh, *wqh, *woh, *yh, *qh, *ql, *kh, *vh;
    cudaGetSymbolAddress((void**)&xh,  g_xh);
    cudaGetSymbolAddress((void**)&wqh, g_wqh);
    cudaGetSymbolAddress((void**)&woh, g_woh);
    cudaGetSymbolAddress((void**)&yh,  g_yh);
    cudaGetSymbolAddress((void**)&qh,  g_q_h);
    cudaGetSymbolAddress((void**)&ql,  g_q_l);
    cudaGetSymbolAddress((void**)&kh,  g_k_h);
    cudaGetSymbolAddress((void**)&vh,  g_v_h);

    cudaFuncSetAttribute(gemm_mma_kernel,
                         cudaFuncAttributeMaxDynamicSharedMemorySize,
                         NSTAGE * STG_B);
    cudaFuncSetAttribute(flash_mma_kernel,
                         cudaFuncAttributeMaxDynamicSharedMemorySize,
                         FLASH_SMEM);

    // 0a. convert x -> fp16
    {
        size_t n = (size_t)M1 * K1;
        split_kernel<<<(unsigned)(n / 4 / 256), 256>>>(x, xh, n);
    }
    // 0b. transpose weights -> fp16
    transpose_split_kernel<<<dim3(N1 / 32, K1 / 32), dim3(32, 8)>>>(Wqkv, wqh, K1, N1);
    transpose_split_kernel<<<dim3(CC / 32, K1 / 32), dim3(32, 8)>>>(Wout, woh, K1, CC);

    // 1. QKV projection + fused RoPE/scale/fp16-split epilogue
    gemm_mma_kernel<<<dim3(N1 / GBN, M1 / GBM), 256, NSTAGE * STG_B>>>(
        xh, wqh, nullptr, qh, ql, kh, vh, 1, M1, N1, K1);

    // 2. Flash attention (writes yh directly)
    flash_mma_kernel<<<dim3(TT / AQ2, BB * HH), 256, FLASH_SMEM>>>(
        qh, ql, kh, vh, yh);

    // 3. Output projection (plain f32 epilogue)
    gemm_mma_kernel<<<dim3(CC / GBN, M1 / GBM), 256, NSTAGE * STG_B>>>(
        yh, woh, out, nullptr, nullptr, nullptr, nullptr, 0, M1, CC, K1);
}

// round 14
// speedup vs baseline: 2.6782x; 1.0505x over previous
#include <cuda_runtime.h>
#include <cuda_fp16.h>
#include <math.h>
#include <stdint.h>

// Problem dims
#define BB 16
#define TT 512
#define CC 2048
#define HH 16
#define HD 128
#define M1 (BB*TT)        // 8192
#define N1 (3*CC)         // 6144
#define K1 CC             // 2048

// ---------------- scratch (device globals; no allocation allowed) ----------
__device__ __half g_xh[(size_t)M1 * K1];
__device__ __half g_wqh[(size_t)N1 * K1];                // Wqkv^T [6144,2048] fp16
__device__ __half g_woh[(size_t)CC * CC];                // Wout^T [2048,2048] fp16
__device__ __half g_yh[(size_t)M1 * CC];
// attention operands (fp16), [B*H, T, 128]: Q hi/lo exact, K/V hi only
__device__ __half g_q_h[(size_t)BB*HH*TT*HD];
__device__ __half g_q_l[(size_t)BB*HH*TT*HD];
__device__ __half g_k_h[(size_t)BB*HH*TT*HD];
__device__ __half g_v_h[(size_t)BB*HH*TT*HD];

// ======================= PTX helpers (baseline ISA only) ===================
__device__ __forceinline__ uint32_t smem_u32(const void* p) {
    uint32_t a;
    asm("{ .reg .u64 t; cvta.to.shared.u64 t, %1; cvt.u32.u64 %0, t; }"
        : "=r"(a) : "l"(p));
    return a;
}
__device__ __forceinline__ void cpasync16(uint32_t dst, const void* src) {
    asm volatile("cp.async.cg.shared.global [%0], [%1], 16;"
                 :: "r"(dst), "l"(src) : "memory");
}
__device__ __forceinline__ void cpasync_commit() {
    asm volatile("cp.async.commit_group;" ::: "memory");
}
__device__ __forceinline__ void cpasync_wait1() {
    asm volatile("cp.async.wait_group 1;" ::: "memory");
}
__device__ __forceinline__ void ldsm_x4(uint32_t& r0, uint32_t& r1,
                                        uint32_t& r2, uint32_t& r3, uint32_t a) {
    asm volatile("ldmatrix.sync.aligned.m8n8.x4.shared.b16 {%0,%1,%2,%3}, [%4];"
                 : "=r"(r0), "=r"(r1), "=r"(r2), "=r"(r3) : "r"(a));
}
__device__ __forceinline__ void ldsm_x4_t(uint32_t& r0, uint32_t& r1,
                                          uint32_t& r2, uint32_t& r3, uint32_t a) {
    asm volatile("ldmatrix.sync.aligned.m8n8.x4.trans.shared.b16 {%0,%1,%2,%3}, [%4];"
                 : "=r"(r0), "=r"(r1), "=r"(r2), "=r"(r3) : "r"(a));
}
// fp16 mma, fp32 accumulate
__device__ __forceinline__ void mma16816f(float* d, const uint32_t* a,
                                          const uint32_t* b) {
    asm volatile(
        "mma.sync.aligned.m16n8k16.row.col.f32.f16.f16.f32 "
        "{%0,%1,%2,%3}, {%4,%5,%6,%7}, {%8,%9}, {%0,%1,%2,%3};"
        : "+f"(d[0]), "+f"(d[1]), "+f"(d[2]), "+f"(d[3])
        : "r"(a[0]), "r"(a[1]), "r"(a[2]), "r"(a[3]), "r"(b[0]), "r"(b[1]));
}
// fp16 hi/lo split of two floats into packed half2 words
__device__ __forceinline__ void split2h(float a, float b, uint32_t& hi, uint32_t& lo) {
    __half ah = __float2half_rn(a), bh = __float2half_rn(b);
    __half al = __float2half_rn(a - __half2float(ah));
    __half bl = __float2half_rn(b - __half2float(bh));
    __half2 h2 = __halves2half2(ah, bh);
    __half2 l2 = __halves2half2(al, bl);
    hi = *reinterpret_cast<uint32_t*>(&h2);
    lo = *reinterpret_cast<uint32_t*>(&l2);
}

// swizzle for 128B rows (GEMM tiles): 16B chunk XOR'd with (row & 7)
__device__ __forceinline__ uint32_t swz128(int row, int chunk) {
    return (uint32_t)((row << 7) + ((chunk ^ (row & 7)) << 4));
}
// swizzle for 256B rows (flash tiles)
__device__ __forceinline__ uint32_t aswz(int row, int chunk) {
    return (uint32_t)((row << 8) + ((chunk ^ (row & 7)) << 4));
}

// ======================= mma.sync fp16 GEMM ================================
// C[M,N] (f32) = Ah[M,K] fp16 @ (Bh [N,K] fp16)^T  -- single product.
// mode 0: store C f32.  mode 1: fused RoPE + scale + fp16 split -> q/k/v.
// K-chunk 64 (128B rows), 3-stage cp.async pipeline, 2 CTAs/SM.
#define GBM 128
#define GBN 128
#define GBK 64
#define TILE_B (128 * 128)           // 16384 B per tile (128 rows x 128B)
#define STG_B  (2 * TILE_B)          // Ah, Bh = 32768
#define NSTAGE 3

__device__ __forceinline__ void g2s_stage(
    uint32_t sbase,
    const __half* __restrict__ Ah, const __half* __restrict__ Bh,
    int m0, int n0, int k0, int K, int tid)
{
#pragma unroll
    for (int i = 0; i < 4; i++) {
        int s = tid + i * 256;               // 0..1023
        int r = s >> 3, c = s & 7;           // row 0..127, 16B chunk 0..7
        uint32_t so = swz128(r, c);
        size_t ga = (size_t)(m0 + r) * K + k0 + c * 8;
        size_t gb = (size_t)(n0 + r) * K + k0 + c * 8;
        cpasync16(sbase + 0 * TILE_B + so, Ah + ga);
        cpasync16(sbase + 1 * TILE_B + so, Bh + gb);
    }
}

__global__ __launch_bounds__(256, 2)
void gemm_mma_kernel(const __half* __restrict__ Ah,
                     const __half* __restrict__ Bh,
                     float* __restrict__ C,
                     __half* __restrict__ Qh, __half* __restrict__ Ql,
                     __half* __restrict__ Kh, __half* __restrict__ Vh,
                     int mode, int M, int N, int K)
{
    extern __shared__ char sm_raw[];
    const uint32_t smbase = smem_u32(sm_raw);
    const int tid = threadIdx.x, wid = tid >> 5, lane = tid & 31;
    const int wm = (wid >> 2) * 64;
    const int wn = (wid & 3) * 32;
    const int m0 = blockIdx.y * GBM;
    const int n0 = blockIdx.x * GBN;
    const int lrow = lane & 15;
    const int lch  = (lane >> 4) & 1;

    float acc[4][4][4];
#pragma unroll
    for (int a = 0; a < 4; a++)
#pragma unroll
        for (int b = 0; b < 4; b++)
#pragma unroll
            for (int c = 0; c < 4; c++) acc[a][b][c] = 0.0f;

    // prologue: fill stages 0,1
    g2s_stage(smbase + 0 * STG_B, Ah, Bh, m0, n0, 0 * GBK, K, tid);
    cpasync_commit();
    g2s_stage(smbase + 1 * STG_B, Ah, Bh, m0, n0, 1 * GBK, K, tid);
    cpasync_commit();

    const int niter = K / GBK;               // 32
    int stage = 0, nstage = 2;
    for (int it = 0; it < niter; ++it) {
        cpasync_wait1();                     // chunk `it` resident
        __syncthreads();

        // refill the stage freed last iter (before compute)
        if (it + 2 < niter)
            g2s_stage(smbase + nstage * STG_B, Ah, Bh,
                      m0, n0, (it + 2) * GBK, K, tid);
        cpasync_commit();
        if (++nstage == NSTAGE) nstage = 0;

        const uint32_t sb = smbase + stage * STG_B;
        if (++stage == NSTAGE) stage = 0;

#pragma unroll
        for (int kb = 0; kb < 4; ++kb) {
            const int chunk = kb * 2 + lch;
            uint32_t ah[4][4];
#pragma unroll
            for (int mf = 0; mf < 4; ++mf) {
                uint32_t off = swz128(wm + mf * 16 + lrow, chunk);
                ldsm_x4(ah[mf][0], ah[mf][1], ah[mf][2], ah[mf][3],
                        sb + 0 * TILE_B + off);
            }
            uint32_t bh[4][2];
#pragma unroll
            for (int np = 0; np < 2; ++np) {
                uint32_t off = swz128(wn + np * 16 + lrow, chunk);
                uint32_t r0, r1, r2, r3;
                ldsm_x4(r0, r1, r2, r3, sb + 1 * TILE_B + off);
                bh[np*2][0] = r0; bh[np*2][1] = r2;
                bh[np*2+1][0] = r1; bh[np*2+1][1] = r3;
            }
#pragma unroll
            for (int mf = 0; mf < 4; ++mf)
#pragma unroll
                for (int nf = 0; nf < 4; ++nf)
                    mma16816f(acc[mf][nf], ah[mf], bh[nf]);
        }
    }

    const int l4 = lane >> 2;
    if (mode == 0) {
        const int l2 = (lane & 3) * 2;
#pragma unroll
        for (int mf = 0; mf < 4; ++mf) {
            int r0 = m0 + wm + mf * 16 + l4;
#pragma unroll
            for (int nf = 0; nf < 4; ++nf) {
                int cx = n0 + wn + nf * 8 + l2;
                *(float2*)&C[(size_t)r0 * N + cx] =
                    make_float2(acc[mf][nf][0], acc[mf][nf][1]);
                *(float2*)&C[(size_t)(r0 + 8) * N + cx] =
                    make_float2(acc[mf][nf][2], acc[mf][nf][3]);
            }
        }
    } else {
        // fused epilogue: this 128-col tile is exactly one head of q/k/v.
        const int which = n0 >> 11;            // 0=q, 1=k, 2=v
        const int hh = (n0 & 2047) >> 7;       // head
        const int l2c = (lane & 3) * 2;
        const float qscale = 0.08838834764831845f;
#pragma unroll
        for (int mf = 0; mf < 4; ++mf) {
#pragma unroll
            for (int hf = 0; hf < 2; ++hf) {
                int row = m0 + wm + mf * 16 + l4 + hf * 8;   // global M row
                int t = row & (TT - 1);
                int bbx = row >> 9;
                size_t dbase = (((size_t)(bbx * HH + hh)) * TT + t) * HD;
                float v[4][2];
#pragma unroll
                for (int nf = 0; nf < 4; ++nf) {
                    v[nf][0] = acc[mf][nf][hf * 2 + 0];
                    v[nf][1] = acc[mf][nf][hf * 2 + 1];
                }
                // RoPE: pairs (d, d+8) live in nf=0/1 of the wn==0 warps
                if (which < 2 && wn == 0) {
#pragma unroll
                    for (int c = 0; c < 2; ++c) {
                        int j = l2c + c;                     // 0..7
                        float inv = powf(10000.0f, -(float)j / 8.0f);
                        float sn, cs;
                        sincosf((float)t * inv, &sn, &cs);
                        float x1 = v[0][c], x2 = v[1][c];
                        v[0][c] = x1 * cs - x2 * sn;
                        v[1][c] = x2 * cs + x1 * sn;
                    }
                }
#pragma unroll
                for (int nf = 0; nf < 4; ++nf) {
                    int d0 = wn + nf * 8 + l2c;
                    float a = v[nf][0], b = v[nf][1];
                    if (which == 0) {
                        a *= qscale; b *= qscale;
                        uint32_t hi2, lo2;
                        split2h(a, b, hi2, lo2);
                        *(uint32_t*)(Qh + dbase + d0) = hi2;
                        *(uint32_t*)(Ql + dbase + d0) = lo2;
                    } else {
                        __half2 p = __floats2half2_rn(a, b);
                        if (which == 1) *(__half2*)(Kh + dbase + d0) = p;
                        else            *(__half2*)(Vh + dbase + d0) = p;
                    }
                }
            }
        }
    }
}

// ======================= conversion kernels ================================
// f32 -> fp16 (hi only)
__global__ __launch_bounds__(256)
void split_kernel(const float* __restrict__ in, __half* __restrict__ hi, size_t n)
{
    size_t i = ((size_t)blockIdx.x * blockDim.x + threadIdx.x) * 4;
    if (i >= n) return;
    float4 x = *(const float4*)(in + i);
    __half2 h0 = __floats2half2_rn(x.x, x.y);
    __half2 h1 = __floats2half2_rn(x.z, x.w);
    uint32_t* hp = (uint32_t*)(hi + i);
    hp[0] = *reinterpret_cast<uint32_t*>(&h0);
    hp[1] = *reinterpret_cast<uint32_t*>(&h1);
}

// W [K,N] f32 -> Th [N,K] fp16 (hi only)
__global__ __launch_bounds__(256)
void transpose_split_kernel(const float* __restrict__ W,
                            __half* __restrict__ Th, int K, int N)
{
    __shared__ float tile[32][33];
    int n0 = blockIdx.x * 32, k0 = blockIdx.y * 32;
    int tx = threadIdx.x, ty = threadIdx.y;   // 32 x 8
#pragma unroll
    for (int i = 0; i < 32; i += 8)
        tile[ty + i][tx] = W[(size_t)(k0 + ty + i) * N + n0 + tx];
    __syncthreads();
#pragma unroll
    for (int i = 0; i < 32; i += 8) {
        float x = tile[tx][ty + i];
        size_t o = (size_t)(n0 + ty + i) * K + k0 + tx;
        Th[o] = __float2half_rn(x);
    }
}

// ---------------- Flash attention (mma.sync fp16, causal) ------------------
// CTA: 128 q-rows (8 warps x 16), kv tile 64, double-buffered KV pipeline.
#define AQ2 128
#define AKV 64
#define Q_TILE_B  (128 * 256)          // 32768 per Q array (hi or lo)
#define KV_TILE_B (64 * 256)           // 16384 per KV array
#define KV_STG_B  (2 * KV_TILE_B)      // Kh, Vh = 32768
#define FLASH_SMEM (2 * Q_TILE_B + 2 * KV_STG_B)   // 131072

__device__ __forceinline__ void kv_stage_load(
    uint32_t skv,
    const __half* __restrict__ Kh, const __half* __restrict__ Vh,
    size_t kg, int tid)
{
#pragma unroll
    for (int i = 0; i < 4; i++) {
        int s = tid + i * 256;            // 0..1023
        int r = s >> 4, c = s & 15;       // 64 rows x 16 chunks
        uint32_t so = aswz(r, c);
        size_t go = kg + (size_t)r * HD + c * 8;
        cpasync16(skv + 0 * KV_TILE_B + so, Kh + go);
        cpasync16(skv + 1 * KV_TILE_B + so, Vh + go);
    }
}

__global__ __launch_bounds__(256)
void flash_mma_kernel(const __half* __restrict__ Qh, const __half* __restrict__ Ql,
                      const __half* __restrict__ Kh, const __half* __restrict__ Vh,
                      __half* __restrict__ Yh)
{
    extern __shared__ char smraw[];
    const uint32_t sbse = smem_u32(smraw);
    const uint32_t sQh = sbse, sQl = sbse + Q_TILE_B;
    const uint32_t sKV0 = sbse + 2 * Q_TILE_B;

    const int tid = threadIdx.x, lane = tid & 31, wid = tid >> 5;
    const int qt = blockIdx.x, bhid = blockIdx.y;
    const int bb = bhid >> 4, hh = bhid & 15;
    const int q0 = qt * AQ2;
    const int l4 = lane >> 2, l2 = lane & 3;
    const int lrow = lane & 15, lch = lane >> 4;
    const int wq = wid * 16;                 // warp q-row base: 0..112

    const int jtmax = 2 * qt + 1;            // kv tiles 0..jtmax

    // G0: Q tile + KV stage 0
    const size_t qg = ((size_t)bhid * TT + q0) * HD;
#pragma unroll
    for (int i = 0; i < 8; i++) {
        int s = tid + i * 256;            // 0..2047
        int r = s >> 4, c = s & 15;       // 128 rows x 16 chunks
        uint32_t so = aswz(r, c);
        size_t go = qg + (size_t)r * HD + c * 8;
        cpasync16(sQh + so, Qh + go);
        cpasync16(sQl + so, Ql + go);
    }
    const size_t kvbase = (size_t)bhid * TT * HD;
    kv_stage_load(sKV0, Kh, Vh, kvbase, tid);
    cpasync_commit();
    kv_stage_load(sKV0 + KV_STG_B, Kh, Vh, kvbase + (size_t)AKV * HD, tid);
    cpasync_commit();

    float m0 = -1e30f, m1 = -1e30f, l0 = 0.0f, l1 = 0.0f;
    float oacc[16][4];
#pragma unroll
    for (int i = 0; i < 16; i++)
#pragma unroll
        for (int j = 0; j < 4; j++) oacc[i][j] = 0.0f;

    for (int jt = 0; jt <= jtmax; ++jt) {
        cpasync_wait1();                 // stage jt resident (one group pending)
        __syncthreads();

        const uint32_t skv = sKV0 + (jt & 1) * KV_STG_B;
        const uint32_t sk_h = skv, sv_h = skv + KV_TILE_B;

        // ---- S = Q K^T (pre-scaled Q; fp32 acc; Q exact via hi/lo) ----
        float sacc[8][4];
#pragma unroll
        for (int i = 0; i < 8; i++)
#pragma unroll
            for (int j = 0; j < 4; j++) sacc[i][j] = 0.0f;

#pragma unroll
        for (int kb = 0; kb < 8; ++kb) {
            const int chunk = kb * 2 + lch;
            const uint32_t qa = aswz(wq + lrow, chunk);
            uint32_t ah[4], al[4];
            ldsm_x4(ah[0], ah[1], ah[2], ah[3], sQh + qa);
            ldsm_x4(al[0], al[1], al[2], al[3], sQl + qa);
#pragma unroll
            for (int np = 0; np < 4; ++np) {
                const uint32_t ka = aswz(np * 16 + lrow, chunk);
                uint32_t r0, r1, r2, r3;
                ldsm_x4(r0, r1, r2, r3, sk_h + ka);
                uint32_t b0[2] = {r0, r2}, b1[2] = {r1, r3};
                mma16816f(sacc[np*2],   ah, b0);
                mma16816f(sacc[np*2],   al, b0);
                mma16816f(sacc[np*2+1], ah, b1);
                mma16816f(sacc[np*2+1], al, b1);
            }
        }

        // ---- causal mask (diagonal-region tiles) ----
        if (jt >= 2 * qt) {
            const int r0g = q0 + wq + l4, r1g = r0g + 8;
#pragma unroll
            for (int nf = 0; nf < 8; ++nf) {
                int c0 = jt * AKV + nf * 8 + 2 * l2;
                if (c0     > r0g) sacc[nf][0] = -1e30f;
                if (c0 + 1 > r0g) sacc[nf][1] = -1e30f;
                if (c0     > r1g) sacc[nf][2] = -1e30f;
                if (c0 + 1 > r1g) sacc[nf][3] = -1e30f;
            }
        }

        // ---- online softmax ----
        float rx0 = -1e30f, rx1 = -1e30f;
#pragma unroll
        for (int nf = 0; nf < 8; ++nf) {
            rx0 = fmaxf(rx0, fmaxf(sacc[nf][0], sacc[nf][1]));
            rx1 = fmaxf(rx1, fmaxf(sacc[nf][2], sacc[nf][3]));
        }
#pragma unroll
        for (int off = 2; off >= 1; off >>= 1) {
            rx0 = fmaxf(rx0, __shfl_xor_sync(0xffffffffu, rx0, off));
            rx1 = fmaxf(rx1, __shfl_xor_sync(0xffffffffu, rx1, off));
        }
        float nm0 = fmaxf(m0, rx0), nm1 = fmaxf(m1, rx1);
        float a0 = __expf(m0 - nm0), a1 = __expf(m1 - nm1);
        m0 = nm0; m1 = nm1;
        float s0 = 0.0f, s1 = 0.0f;
#pragma unroll
        for (int nf = 0; nf < 8; ++nf) {
            sacc[nf][0] = __expf(sacc[nf][0] - nm0); s0 += sacc[nf][0];
            sacc[nf][1] = __expf(sacc[nf][1] - nm0); s0 += sacc[nf][1];
            sacc[nf][2] = __expf(sacc[nf][2] - nm1); s1 += sacc[nf][2];
            sacc[nf][3] = __expf(sacc[nf][3] - nm1); s1 += sacc[nf][3];
        }
#pragma unroll
        for (int off = 2; off >= 1; off >>= 1) {
            s0 += __shfl_xor_sync(0xffffffffu, s0, off);
            s1 += __shfl_xor_sync(0xffffffffu, s1, off);
        }
        l0 = l0 * a0 + s0;
        l1 = l1 * a1 + s1;
#pragma unroll
        for (int nt = 0; nt < 16; ++nt) {
            oacc[nt][0] *= a0; oacc[nt][1] *= a0;
            oacc[nt][2] *= a1; oacc[nt][3] *= a1;
        }

        // ---- O += P V (P exact via fp16 hi/lo; V fp16 hi) ----
#pragma unroll
        for (int kt = 0; kt < 4; ++kt) {
            uint32_t ph[4], pl[4];
            split2h(sacc[2*kt][0],   sacc[2*kt][1],   ph[0], pl[0]);
            split2h(sacc[2*kt][2],   sacc[2*kt][3],   ph[1], pl[1]);
            split2h(sacc[2*kt+1][0], sacc[2*kt+1][1], ph[2], pl[2]);
            split2h(sacc[2*kt+1][2], sacc[2*kt+1][3], ph[3], pl[3]);
#pragma unroll
            for (int nd = 0; nd < 8; ++nd) {
                const uint32_t va = aswz(kt * 16 + lrow, nd * 2 + lch);
                uint32_t h0, h1, h2, h3;
                ldsm_x4_t(h0, h1, h2, h3, sv_h + va);
                uint32_t vb0[2] = {h0, h1}, vb1[2] = {h2, h3};
                mma16816f(oacc[nd*2],   ph, vb0);
                mma16816f(oacc[nd*2],   pl, vb0);
                mma16816f(oacc[nd*2+1], ph, vb1);
                mma16816f(oacc[nd*2+1], pl, vb1);
            }
        }

        // refill the stage just consumed (stage jt&1) for tile jt+2
        __syncthreads();
        if (jt + 2 <= jtmax)
            kv_stage_load(sKV0 + (jt & 1) * KV_STG_B, Kh, Vh,
                          kvbase + (size_t)(jt + 2) * AKV * HD, tid);
        cpasync_commit();                // one group per iter (may be empty)
    }

    // ---- epilogue: normalize, fp16 round, write Yh [B,T,C] ----
    const float il0 = 1.0f / l0, il1 = 1.0f / l1;
    const int r0g = q0 + wq + l4, r1g = r0g + 8;
#pragma unroll
    for (int nt = 0; nt < 16; ++nt) {
        int col = hh * HD + nt * 8 + 2 * l2;
        size_t o0 = ((size_t)bb * TT + r0g) * CC + col;
        size_t o1 = ((size_t)bb * TT + r1g) * CC + col;
        __half2 p0 = __floats2half2_rn(oacc[nt][0] * il0, oacc[nt][1] * il0);
        __half2 p1 = __floats2half2_rn(oacc[nt][2] * il1, oacc[nt][3] * il1);
        *(__half2*)(Yh + o0) = p0;
        *(__half2*)(Yh + o1) = p1;
    }
}

// ---------------- launch ----------------------------------------------------
extern "C" void kernel_launch(void* const* d_in, const int* in_sizes, int n_in,
                              void* d_out, int out_size)
{
    const float* x    = (const float*)d_in[0];
    const float* Wqkv = (const float*)d_in[1];
    const float* Wout = (const float*)d_in[2];
    float* out = (float*)d_out;

    __half *xh, *wqh, *woh, *yh, *qh, *ql, *kh, *vh;
    cudaGetSymbolAddress((void**)&xh,  g_xh);
    cudaGetSymbolAddress((void**)&wqh, g_wqh);
    cudaGetSymbolAddress((void**)&woh, g_woh);
    cudaGetSymbolAddress((void**)&yh,  g_yh);
    cudaGetSymbolAddress((void**)&qh,  g_q_h);
    cudaGetSymbolAddress((void**)&ql,  g_q_l);
    cudaGetSymbolAddress((void**)&kh,  g_k_h);
    cudaGetSymbolAddress((void**)&vh,  g_v_h);

    cudaFuncSetAttribute(gemm_mma_kernel,
                         cudaFuncAttributeMaxDynamicSharedMemorySize,
                         NSTAGE * STG_B);
    cudaFuncSetAttribute(flash_mma_kernel,
                         cudaFuncAttributeMaxDynamicSharedMemorySize,
                         FLASH_SMEM);

    // 0a. convert x -> fp16
    {
        size_t n = (size_t)M1 * K1;
        split_kernel<<<(unsigned)(n / 4 / 256), 256>>>(x, xh, n);
    }
    // 0b. transpose weights -> fp16
    transpose_split_kernel<<<dim3(N1 / 32, K1 / 32), dim3(32, 8)>>>(Wqkv, wqh, K1, N1);
    transpose_split_kernel<<<dim3(CC / 32, K1 / 32), dim3(32, 8)>>>(Wout, woh, K1, CC);

    // 1. QKV projection + fused RoPE/scale/fp16-split epilogue
    gemm_mma_kernel<<<dim3(N1 / GBN, M1 / GBM), 256, NSTAGE * STG_B>>>(
        xh, wqh, nullptr, qh, ql, kh, vh, 1, M1, N1, K1);

    // 2. Flash attention (writes yh directly)
    flash_mma_kernel<<<dim3(TT / AQ2, BB * HH), 256, FLASH_SMEM>>>(
        qh, ql, kh, vh, yh);

    // 3. Output projection (plain f32 epilogue)
    gemm_mma_kernel<<<dim3(CC / GBN, M1 / GBM), 256, NSTAGE * STG_B>>>(
        yh, woh, out, nullptr, nullptr, nullptr, nullptr, 0, M1, CC, K1);
}

// round 16
// speedup vs baseline: 2.7449x; 1.0249x over previous
#include <cuda_runtime.h>
#include <cuda_fp16.h>
#include <math.h>
#include <stdint.h>

// Problem dims
#define BB 16
#define TT 512
#define CC 2048
#define HH 16
#define HD 128
#define M1 (BB*TT)        // 8192
#define N1 (3*CC)         // 6144
#define K1 CC             // 2048

// ---------------- scratch (device globals; no allocation allowed) ----------
__device__ __half g_xh[(size_t)M1 * K1];
__device__ __half g_wqh[(size_t)N1 * K1];                // Wqkv^T [6144,2048] fp16
__device__ __half g_woh[(size_t)CC * CC];                // Wout^T [2048,2048] fp16
__device__ __half g_yh[(size_t)M1 * CC];
// attention operands (fp16), [B*H, T, 128]: Q hi/lo exact, K/V hi only
__device__ __half g_q_h[(size_t)BB*HH*TT*HD];
__device__ __half g_q_l[(size_t)BB*HH*TT*HD];
__device__ __half g_k_h[(size_t)BB*HH*TT*HD];
__device__ __half g_v_h[(size_t)BB*HH*TT*HD];

// ======================= PTX helpers (baseline ISA only) ===================
__device__ __forceinline__ uint32_t smem_u32(const void* p) {
    uint32_t a;
    asm("{ .reg .u64 t; cvta.to.shared.u64 t, %1; cvt.u32.u64 %0, t; }"
        : "=r"(a) : "l"(p));
    return a;
}
__device__ __forceinline__ void cpasync16(uint32_t dst, const void* src) {
    asm volatile("cp.async.cg.shared.global [%0], [%1], 16;"
                 :: "r"(dst), "l"(src) : "memory");
}
__device__ __forceinline__ void cpasync_commit() {
    asm volatile("cp.async.commit_group;" ::: "memory");
}
__device__ __forceinline__ void cpasync_wait1() {
    asm volatile("cp.async.wait_group 1;" ::: "memory");
}
__device__ __forceinline__ void ldsm_x4(uint32_t& r0, uint32_t& r1,
                                        uint32_t& r2, uint32_t& r3, uint32_t a) {
    asm volatile("ldmatrix.sync.aligned.m8n8.x4.shared.b16 {%0,%1,%2,%3}, [%4];"
                 : "=r"(r0), "=r"(r1), "=r"(r2), "=r"(r3) : "r"(a));
}
__device__ __forceinline__ void ldsm_x4_t(uint32_t& r0, uint32_t& r1,
                                          uint32_t& r2, uint32_t& r3, uint32_t a) {
    asm volatile("ldmatrix.sync.aligned.m8n8.x4.trans.shared.b16 {%0,%1,%2,%3}, [%4];"
                 : "=r"(r0), "=r"(r1), "=r"(r2), "=r"(r3) : "r"(a));
}
// fp16 mma, fp32 accumulate
__device__ __forceinline__ void mma16816f(float* d, const uint32_t* a,
                                          const uint32_t* b) {
    asm volatile(
        "mma.sync.aligned.m16n8k16.row.col.f32.f16.f16.f32 "
        "{%0,%1,%2,%3}, {%4,%5,%6,%7}, {%8,%9}, {%0,%1,%2,%3};"
        : "+f"(d[0]), "+f"(d[1]), "+f"(d[2]), "+f"(d[3])
        : "r"(a[0]), "r"(a[1]), "r"(a[2]), "r"(a[3]), "r"(b[0]), "r"(b[1]));
}
// fp16 hi/lo split of two floats into packed half2 words
__device__ __forceinline__ void split2h(float a, float b, uint32_t& hi, uint32_t& lo) {
    __half ah = __float2half_rn(a), bh = __float2half_rn(b);
    __half al = __float2half_rn(a - __half2float(ah));
    __half bl = __float2half_rn(b - __half2float(bh));
    __half2 h2 = __halves2half2(ah, bh);
    __half2 l2 = __halves2half2(al, bl);
    hi = *reinterpret_cast<uint32_t*>(&h2);
    lo = *reinterpret_cast<uint32_t*>(&l2);
}

// swizzle for 128B rows (GEMM tiles): 16B chunk XOR'd with (row & 7)
__device__ __forceinline__ uint32_t swz128(int row, int chunk) {
    return (uint32_t)((row << 7) + ((chunk ^ (row & 7)) << 4));
}
// swizzle for 256B rows (flash tiles)
__device__ __forceinline__ uint32_t aswz(int row, int chunk) {
    return (uint32_t)((row << 8) + ((chunk ^ (row & 7)) << 4));
}

// ======================= mma.sync fp16 GEMM ================================
// C[M,N] (f32) = Ah[M,K] fp16 @ (Bh [N,K] fp16)^T  -- single product.
// mode 0: store C f32.  mode 1: fused RoPE + scale + fp16 split -> q/k/v.
// CTA 128x128, 128 threads (2x2 warps, warp tile 64x64), GBK=64,
// 3-stage cp.async pipeline, 2 CTAs/SM.
#define GBM 128
#define GBN 128
#define GBK 64
#define TILE_B (128 * 128)           // 16384 B per tile (128 rows x 128B)
#define STG_B  (2 * TILE_B)          // Ah, Bh = 32768
#define NSTAGE 3

__device__ __forceinline__ void g2s_stage(
    uint32_t sbase,
    const __half* __restrict__ Ah, const __half* __restrict__ Bh,
    int m0, int n0, int k0, int K, int tid)
{
#pragma unroll
    for (int i = 0; i < 8; i++) {
        int s = tid + i * 128;               // 0..1023
        int r = s >> 3, c = s & 7;           // row 0..127, 16B chunk 0..7
        uint32_t so = swz128(r, c);
        size_t ga = (size_t)(m0 + r) * K + k0 + c * 8;
        size_t gb = (size_t)(n0 + r) * K + k0 + c * 8;
        cpasync16(sbase + 0 * TILE_B + so, Ah + ga);
        cpasync16(sbase + 1 * TILE_B + so, Bh + gb);
    }
}

__global__ __launch_bounds__(128, 2)
void gemm_mma_kernel(const __half* __restrict__ Ah,
                     const __half* __restrict__ Bh,
                     float* __restrict__ C,
                     __half* __restrict__ Qh, __half* __restrict__ Ql,
                     __half* __restrict__ Kh, __half* __restrict__ Vh,
                     int mode, int M, int N, int K)
{
    extern __shared__ char sm_raw[];
    const uint32_t smbase = smem_u32(sm_raw);
    const int tid = threadIdx.x, wid = tid >> 5, lane = tid & 31;
    const int wm = (wid >> 1) * 64;          // warp M offset: 0 / 64
    const int wn = (wid & 1) * 64;           // warp N offset: 0 / 64
    const int m0 = blockIdx.y * GBM;
    const int n0 = blockIdx.x * GBN;
    const int lrow = lane & 15;
    const int lch  = (lane >> 4) & 1;

    float acc[4][8][4];
#pragma unroll
    for (int a = 0; a < 4; a++)
#pragma unroll
        for (int b = 0; b < 8; b++)
#pragma unroll
            for (int c = 0; c < 4; c++) acc[a][b][c] = 0.0f;

    // prologue: fill stages 0,1
    g2s_stage(smbase + 0 * STG_B, Ah, Bh, m0, n0, 0 * GBK, K, tid);
    cpasync_commit();
    g2s_stage(smbase + 1 * STG_B, Ah, Bh, m0, n0, 1 * GBK, K, tid);
    cpasync_commit();

    const int niter = K / GBK;               // 32
    int stage = 0, nstage = 2;
    for (int it = 0; it < niter; ++it) {
        cpasync_wait1();                     // chunk `it` resident
        __syncthreads();

        // refill the stage freed last iter (before compute)
        if (it + 2 < niter)
            g2s_stage(smbase + nstage * STG_B, Ah, Bh,
                      m0, n0, (it + 2) * GBK, K, tid);
        cpasync_commit();
        if (++nstage == NSTAGE) nstage = 0;

        const uint32_t sb = smbase + stage * STG_B;
        if (++stage == NSTAGE) stage = 0;

#pragma unroll
        for (int kb = 0; kb < 4; ++kb) {
            const int chunk = kb * 2 + lch;
            uint32_t ah[4][4];
#pragma unroll
            for (int mf = 0; mf < 4; ++mf) {
                uint32_t off = swz128(wm + mf * 16 + lrow, chunk);
                ldsm_x4(ah[mf][0], ah[mf][1], ah[mf][2], ah[mf][3],
                        sb + 0 * TILE_B + off);
            }
            uint32_t bh[8][2];
#pragma unroll
            for (int np = 0; np < 4; ++np) {
                uint32_t off = swz128(wn + np * 16 + lrow, chunk);
                uint32_t r0, r1, r2, r3;
                ldsm_x4(r0, r1, r2, r3, sb + 1 * TILE_B + off);
                bh[np*2][0] = r0; bh[np*2][1] = r2;
                bh[np*2+1][0] = r1; bh[np*2+1][1] = r3;
            }
#pragma unroll
            for (int mf = 0; mf < 4; ++mf)
#pragma unroll
                for (int nf = 0; nf < 8; ++nf)
                    mma16816f(acc[mf][nf], ah[mf], bh[nf]);
        }
    }

    const int l4 = lane >> 2;
    if (mode == 0) {
        const int l2 = (lane & 3) * 2;
#pragma unroll
        for (int mf = 0; mf < 4; ++mf) {
            int r0 = m0 + wm + mf * 16 + l4;
#pragma unroll
            for (int nf = 0; nf < 8; ++nf) {
                int cx = n0 + wn + nf * 8 + l2;
                *(float2*)&C[(size_t)r0 * N + cx] =
                    make_float2(acc[mf][nf][0], acc[mf][nf][1]);
                *(float2*)&C[(size_t)(r0 + 8) * N + cx] =
                    make_float2(acc[mf][nf][2], acc[mf][nf][3]);
            }
        }
    } else {
        // fused epilogue: this 128-col tile is exactly one head of q/k/v.
        const int which = n0 >> 11;            // 0=q, 1=k, 2=v
        const int hh = (n0 & 2047) >> 7;       // head
        const int l2c = (lane & 3) * 2;
        const float qscale = 0.08838834764831845f;
#pragma unroll
        for (int mf = 0; mf < 4; ++mf) {
#pragma unroll
            for (int hf = 0; hf < 2; ++hf) {
                int row = m0 + wm + mf * 16 + l4 + hf * 8;   // global M row
                int t = row & (TT - 1);
                int bbx = row >> 9;
                size_t dbase = (((size_t)(bbx * HH + hh)) * TT + t) * HD;
                float v[8][2];
#pragma unroll
                for (int nf = 0; nf < 8; ++nf) {
                    v[nf][0] = acc[mf][nf][hf * 2 + 0];
                    v[nf][1] = acc[mf][nf][hf * 2 + 1];
                }
                // RoPE: pairs (d, d+8) live in nf=0/1 of the wn==0 warps
                if (which < 2 && wn == 0) {
#pragma unroll
                    for (int c = 0; c < 2; ++c) {
                        int j = l2c + c;                     // 0..7
                        float inv = powf(10000.0f, -(float)j / 8.0f);
                        float sn, cs;
                        sincosf((float)t * inv, &sn, &cs);
                        float x1 = v[0][c], x2 = v[1][c];
                        v[0][c] = x1 * cs - x2 * sn;
                        v[1][c] = x2 * cs + x1 * sn;
                    }
                }
#pragma unroll
                for (int nf = 0; nf < 8; ++nf) {
                    int d0 = wn + nf * 8 + l2c;
                    float a = v[nf][0], b = v[nf][1];
                    if (which == 0) {
                        a *= qscale; b *= qscale;
                        uint32_t hi2, lo2;
                        split2h(a, b, hi2, lo2);
                        *(uint32_t*)(Qh + dbase + d0) = hi2;
                        *(uint32_t*)(Ql + dbase + d0) = lo2;
                    } else {
                        __half2 p = __floats2half2_rn(a, b);
                        if (which == 1) *(__half2*)(Kh + dbase + d0) = p;
                        else            *(__half2*)(Vh + dbase + d0) = p;
                    }
                }
            }
        }
    }
}

// ======================= conversion kernels ================================
// f32 -> fp16 (hi only)
__global__ __launch_bounds__(256)
void split_kernel(const float* __restrict__ in, __half* __restrict__ hi, size_t n)
{
    size_t i = ((size_t)blockIdx.x * blockDim.x + threadIdx.x) * 4;
    if (i >= n) return;
    float4 x = *(const float4*)(in + i);
    __half2 h0 = __floats2half2_rn(x.x, x.y);
    __half2 h1 = __floats2half2_rn(x.z, x.w);
    uint32_t* hp = (uint32_t*)(hi + i);
    hp[0] = *reinterpret_cast<uint32_t*>(&h0);
    hp[1] = *reinterpret_cast<uint32_t*>(&h1);
}

// W [K,N] f32 -> Th [N,K] fp16 (hi only)
__global__ __launch_bounds__(256)
void transpose_split_kernel(const float* __restrict__ W,
                            __half* __restrict__ Th, int K, int N)
{
    __shared__ float tile[32][33];
    int n0 = blockIdx.x * 32, k0 = blockIdx.y * 32;
    int tx = threadIdx.x, ty = threadIdx.y;   // 32 x 8
#pragma unroll
    for (int i = 0; i < 32; i += 8)
        tile[ty + i][tx] = W[(size_t)(k0 + ty + i) * N + n0 + tx];
    __syncthreads();
#pragma unroll
    for (int i = 0; i < 32; i += 8) {
        float x = tile[tx][ty + i];
        size_t o = (size_t)(n0 + ty + i) * K + k0 + tx;
        Th[o] = __float2half_rn(x);
    }
}

// ---------------- Flash attention (mma.sync fp16, causal) ------------------
// CTA: 128 q-rows (8 warps x 16), kv tile 64, double-buffered KV pipeline.
#define AQ2 128
#define AKV 64
#define Q_TILE_B  (128 * 256)          // 32768 per Q array (hi or lo)
#define KV_TILE_B (64 * 256)           // 16384 per KV array
#define KV_STG_B  (2 * KV_TILE_B)      // Kh, Vh = 32768
#define FLASH_SMEM (2 * Q_TILE_B + 2 * KV_STG_B)   // 131072

__device__ __forceinline__ void kv_stage_load(
    uint32_t skv,
    const __half* __restrict__ Kh, const __half* __restrict__ Vh,
    size_t kg, int tid)
{
#pragma unroll
    for (int i = 0; i < 4; i++) {
        int s = tid + i * 256;            // 0..1023
        int r = s >> 4, c = s & 15;       // 64 rows x 16 chunks
        uint32_t so = aswz(r, c);
        size_t go = kg + (size_t)r * HD + c * 8;
        cpasync16(skv + 0 * KV_TILE_B + so, Kh + go);
        cpasync16(skv + 1 * KV_TILE_B + so, Vh + go);
    }
}

__global__ __launch_bounds__(256)
void flash_mma_kernel(const __half* __restrict__ Qh, const __half* __restrict__ Ql,
                      const __half* __restrict__ Kh, const __half* __restrict__ Vh,
                      __half* __restrict__ Yh)
{
    extern __shared__ char smraw[];
    const uint32_t sbse = smem_u32(smraw);
    const uint32_t sQh = sbse, sQl = sbse + Q_TILE_B;
    const uint32_t sKV0 = sbse + 2 * Q_TILE_B;

    const int tid = threadIdx.x, lane = tid & 31, wid = tid >> 5;
    const int qt = blockIdx.x, bhid = blockIdx.y;
    const int bb = bhid >> 4, hh = bhid & 15;
    const int q0 = qt * AQ2;
    const int l4 = lane >> 2, l2 = lane & 3;
    const int lrow = lane & 15, lch = lane >> 4;
    const int wq = wid * 16;                 // warp q-row base: 0..112

    const int jtmax = 2 * qt + 1;            // kv tiles 0..jtmax

    // G0: Q tile + KV stage 0
    const size_t qg = ((size_t)bhid * TT + q0) * HD;
#pragma unroll
    for (int i = 0; i < 8; i++) {
        int s = tid + i * 256;            // 0..2047
        int r = s >> 4, c = s & 15;       // 128 rows x 16 chunks
        uint32_t so = aswz(r, c);
        size_t go = qg + (size_t)r * HD + c * 8;
        cpasync16(sQh + so, Qh + go);
        cpasync16(sQl + so, Ql + go);
    }
    const size_t kvbase = (size_t)bhid * TT * HD;
    kv_stage_load(sKV0, Kh, Vh, kvbase, tid);
    cpasync_commit();
    kv_stage_load(sKV0 + KV_STG_B, Kh, Vh, kvbase + (size_t)AKV * HD, tid);
    cpasync_commit();

    float m0 = -1e30f, m1 = -1e30f, l0 = 0.0f, l1 = 0.0f;
    float oacc[16][4];
#pragma unroll
    for (int i = 0; i < 16; i++)
#pragma unroll
        for (int j = 0; j < 4; j++) oacc[i][j] = 0.0f;

    for (int jt = 0; jt <= jtmax; ++jt) {
        cpasync_wait1();                 // stage jt resident (one group pending)
        __syncthreads();

        const uint32_t skv = sKV0 + (jt & 1) * KV_STG_B;
        const uint32_t sk_h = skv, sv_h = skv + KV_TILE_B;

        // ---- S = Q K^T (pre-scaled Q; fp32 acc; Q exact via hi/lo) ----
        float sacc[8][4];
#pragma unroll
        for (int i = 0; i < 8; i++)
#pragma unroll
            for (int j = 0; j < 4; j++) sacc[i][j] = 0.0f;

#pragma unroll
        for (int kb = 0; kb < 8; ++kb) {
            const int chunk = kb * 2 + lch;
            const uint32_t qa = aswz(wq + lrow, chunk);
            uint32_t ah[4], al[4];
            ldsm_x4(ah[0], ah[1], ah[2], ah[3], sQh + qa);
            ldsm_x4(al[0], al[1], al[2], al[3], sQl + qa);
#pragma unroll
            for (int np = 0; np < 4; ++np) {
                const uint32_t ka = aswz(np * 16 + lrow, chunk);
                uint32_t r0, r1, r2, r3;
                ldsm_x4(r0, r1, r2, r3, sk_h + ka);
                uint32_t b0[2] = {r0, r2}, b1[2] = {r1, r3};
                mma16816f(sacc[np*2],   ah, b0);
                mma16816f(sacc[np*2],   al, b0);
                mma16816f(sacc[np*2+1], ah, b1);
                mma16816f(sacc[np*2+1], al, b1);
            }
        }

        // ---- causal mask (diagonal-region tiles) ----
        if (jt >= 2 * qt) {
            const int r0g = q0 + wq + l4, r1g = r0g + 8;
#pragma unroll
            for (int nf = 0; nf < 8; ++nf) {
                int c0 = jt * AKV + nf * 8 + 2 * l2;
                if (c0     > r0g) sacc[nf][0] = -1e30f;
                if (c0 + 1 > r0g) sacc[nf][1] = -1e30f;
                if (c0     > r1g) sacc[nf][2] = -1e30f;
                if (c0 + 1 > r1g) sacc[nf][3] = -1e30f;
            }
        }

        // ---- online softmax ----
        float rx0 = -1e30f, rx1 = -1e30f;
#pragma unroll
        for (int nf = 0; nf < 8; ++nf) {
            rx0 = fmaxf(rx0, fmaxf(sacc[nf][0], sacc[nf][1]));
            rx1 = fmaxf(rx1, fmaxf(sacc[nf][2], sacc[nf][3]));
        }
#pragma unroll
        for (int off = 2; off >= 1; off >>= 1) {
            rx0 = fmaxf(rx0, __shfl_xor_sync(0xffffffffu, rx0, off));
            rx1 = fmaxf(rx1, __shfl_xor_sync(0xffffffffu, rx1, off));
        }
        float nm0 = fmaxf(m0, rx0), nm1 = fmaxf(m1, rx1);
        float a0 = __expf(m0 - nm0), a1 = __expf(m1 - nm1);
        m0 = nm0; m1 = nm1;
        float s0 = 0.0f, s1 = 0.0f;
#pragma unroll
        for (int nf = 0; nf < 8; ++nf) {
            sacc[nf][0] = __expf(sacc[nf][0] - nm0); s0 += sacc[nf][0];
            sacc[nf][1] = __expf(sacc[nf][1] - nm0); s0 += sacc[nf][1];
            sacc[nf][2] = __expf(sacc[nf][2] - nm1); s1 += sacc[nf][2];
            sacc[nf][3] = __expf(sacc[nf][3] - nm1); s1 += sacc[nf][3];
        }
#pragma unroll
        for (int off = 2; off >= 1; off >>= 1) {
            s0 += __shfl_xor_sync(0xffffffffu, s0, off);
            s1 += __shfl_xor_sync(0xffffffffu, s1, off);
        }
        l0 = l0 * a0 + s0;
        l1 = l1 * a1 + s1;
#pragma unroll
        for (int nt = 0; nt < 16; ++nt) {
            oacc[nt][0] *= a0; oacc[nt][1] *= a0;
            oacc[nt][2] *= a1; oacc[nt][3] *= a1;
        }

        // ---- O += P V (P exact via fp16 hi/lo; V fp16 hi) ----
#pragma unroll
        for (int kt = 0; kt < 4; ++kt) {
            uint32_t ph[4], pl[4];
            split2h(sacc[2*kt][0],   sacc[2*kt][1],   ph[0], pl[0]);
            split2h(sacc[2*kt][2],   sacc[2*kt][3],   ph[1], pl[1]);
            split2h(sacc[2*kt+1][0], sacc[2*kt+1][1], ph[2], pl[2]);
            split2h(sacc[2*kt+1][2], sacc[2*kt+1][3], ph[3], pl[3]);
#pragma unroll
            for (int nd = 0; nd < 8; ++nd) {
                const uint32_t va = aswz(kt * 16 + lrow, nd * 2 + lch);
                uint32_t h0, h1, h2, h3;
                ldsm_x4_t(h0, h1, h2, h3, sv_h + va);
                uint32_t vb0[2] = {h0, h1}, vb1[2] = {h2, h3};
                mma16816f(oacc[nd*2],   ph, vb0);
                mma16816f(oacc[nd*2],   pl, vb0);
                mma16816f(oacc[nd*2+1], ph, vb1);
                mma16816f(oacc[nd*2+1], pl, vb1);
            }
        }

        // refill the stage just consumed (stage jt&1) for tile jt+2
        __syncthreads();
        if (jt + 2 <= jtmax)
            kv_stage_load(sKV0 + (jt & 1) * KV_STG_B, Kh, Vh,
                          kvbase + (size_t)(jt + 2) * AKV * HD, tid);
        cpasync_commit();                // one group per iter (may be empty)
    }

    // ---- epilogue: normalize, fp16 round, write Yh [B,T,C] ----
    const float il0 = 1.0f / l0, il1 = 1.0f / l1;
    const int r0g = q0 + wq + l4, r1g = r0g + 8;
#pragma unroll
    for (int nt = 0; nt < 16; ++nt) {
        int col = hh * HD + nt * 8 + 2 * l2;
        size_t o0 = ((size_t)bb * TT + r0g) * CC + col;
        size_t o1 = ((size_t)bb * TT + r1g) * CC + col;
        __half2 p0 = __floats2half2_rn(oacc[nt][0] * il0, oacc[nt][1] * il0);
        __half2 p1 = __floats2half2_rn(oacc[nt][2] * il1, oacc[nt][3] * il1);
        *(__half2*)(Yh + o0) = p0;
        *(__half2*)(Yh + o1) = p1;
    }
}

// ---------------- launch ----------------------------------------------------
extern "C" void kernel_launch(void* const* d_in, const int* in_sizes, int n_in,
                              void* d_out, int out_size)
{
    const float* x    = (const float*)d_in[0];
    const float* Wqkv = (const float*)d_in[1];
    const float* Wout = (const float*)d_in[2];
    float* out = (float*)d_out;

    __half *xh, *wqh, *woh, *yh, *qh, *ql, *kh, *vh;
    cudaGetSymbolAddress((void**)&xh,  g_xh);
    cudaGetSymbolAddress((void**)&wqh, g_wqh);
    cudaGetSymbolAddress((void**)&woh, g_woh);
    cudaGetSymbolAddress((void**)&yh,  g_yh);
    cudaGetSymbolAddress((void**)&qh,  g_q_h);
    cudaGetSymbolAddress((void**)&ql,  g_q_l);
    cudaGetSymbolAddress((void**)&kh,  g_k_h);
    cudaGetSymbolAddress((void**)&vh,  g_v_h);

    cudaFuncSetAttribute(gemm_mma_kernel,
                         cudaFuncAttributeMaxDynamicSharedMemorySize,
                         NSTAGE * STG_B);
    cudaFuncSetAttribute(flash_mma_kernel,
                         cudaFuncAttributeMaxDynamicSharedMemorySize,
                         FLASH_SMEM);

    // 0a. convert x -> fp16
    {
        size_t n = (size_t)M1 * K1;
        split_kernel<<<(unsigned)(n / 4 / 256), 256>>>(x, xh, n);
    }
    // 0b. transpose weights -> fp16
    transpose_split_kernel<<<dim3(N1 / 32, K1 / 32), dim3(32, 8)>>>(Wqkv, wqh, K1, N1);
    transpose_split_kernel<<<dim3(CC / 32, K1 / 32), dim3(32, 8)>>>(Wout, woh, K1, CC);

    // 1. QKV projection + fused RoPE/scale/fp16-split epilogue
    gemm_mma_kernel<<<dim3(N1 / GBN, M1 / GBM), 128, NSTAGE * STG_B>>>(
        xh, wqh, nullptr, qh, ql, kh, vh, 1, M1, N1, K1);

    // 2. Flash attention (writes yh directly)
    flash_mma_kernel<<<dim3(TT / AQ2, BB * HH), 256, FLASH_SMEM>>>(
        qh, ql, kh, vh, yh);

    // 3. Output projection (plain f32 epilogue)
    gemm_mma_kernel<<<dim3(CC / GBN, M1 / GBM), 128, NSTAGE * STG_B>>>(
        yh, woh, out, nullptr, nullptr, nullptr, nullptr, 0, M1, CC, K1);
}